// round 8
// baseline (speedup 1.0000x reference)
#include <cuda_runtime.h>
#include <cuda_fp16.h>
#include <cstdint>
#include <cstddef>

#define PR_N      16384
#define PR_INDIM  256
#define PR_D      128
#define LOG2E     1.4426950408889634f

// ---------------- fp16 split scratch (hi+lo ~= 22-bit mantissa) -------------
__device__ __align__(16) __half g_Qhi[PR_N * PR_D];
__device__ __align__(16) __half g_Qlo[PR_N * PR_D];
__device__ __align__(16) __half g_Khi[PR_N * PR_D];
__device__ __align__(16) __half g_Klo[PR_N * PR_D];
__device__ __align__(16) __half g_VTh[PR_D * PR_N];   // V transposed [d][n], fp16

// ---------------- helpers ---------------------------------------------------
__device__ __forceinline__ uint32_t smem_u32(const void* p) {
    uint32_t a;
    asm("{ .reg .u64 t; cvta.to.shared.u64 t, %1; cvt.u32.u64 %0, t; }"
        : "=r"(a) : "l"(p));
    return a;
}
__device__ __forceinline__ float ex2f(float x) {   // MUFU.EX2
    float r;
    asm("ex2.approx.ftz.f32 %0, %1;" : "=f"(r) : "f"(x));
    return r;
}
__device__ __forceinline__ uint32_t pack_f16x2(float a, float b) {
    uint32_t r;
    asm("cvt.rn.f16x2.f32 %0, %1, %2;" : "=r"(r) : "f"(b), "f"(a));
    return r;
}
__device__ __forceinline__ void split2h(float f0, float f1, uint32_t& hi, uint32_t& lo) {
    __half a0 = __float2half_rn(f0), a1 = __float2half_rn(f1);
    hi = ((uint32_t)__half_as_ushort(a1) << 16) | __half_as_ushort(a0);
    lo = pack_f16x2(f0 - __half2float(a0), f1 - __half2float(a1));
}
__device__ __forceinline__ void ldmx4(uint32_t* r, uint32_t addr) {
    asm volatile("ldmatrix.sync.aligned.m8n8.x4.shared.b16 {%0,%1,%2,%3}, [%4];"
                 : "=r"(r[0]), "=r"(r[1]), "=r"(r[2]), "=r"(r[3]) : "r"(addr));
}
__device__ __forceinline__ void mma16816h(float* c, const uint32_t* a,
                                          const uint32_t* b) {
    asm volatile(
        "mma.sync.aligned.m16n8k16.row.col.f32.f16.f16.f32 "
        "{%0,%1,%2,%3}, {%4,%5,%6,%7}, {%8,%9}, {%0,%1,%2,%3};"
        : "+f"(c[0]), "+f"(c[1]), "+f"(c[2]), "+f"(c[3])
        : "r"(a[0]), "r"(a[1]), "r"(a[2]), "r"(a[3]), "r"(b[0]), "r"(b[1]));
}
__device__ __forceinline__ void cp16(uint32_t dst, const void* src) {
    asm volatile("cp.async.cg.shared.global [%0], [%1], 16;"
                 :: "r"(dst), "l"(src) : "memory");
}
__device__ __forceinline__ void cp_commit() {
    asm volatile("cp.async.commit_group;" ::: "memory");
}
__device__ __forceinline__ void cp_wait2() {
    asm volatile("cp.async.wait_group 2;" ::: "memory");
}
__device__ __forceinline__ void cp_wait0() {
    asm volatile("cp.async.wait_group 0;" ::: "memory");
}

// ---------------------------------------------------------------------------
// Kernel 1: QKV projection + fp16 split + V transpose.  grid=256, block=256.
// ---------------------------------------------------------------------------
__global__ void __launch_bounds__(256) pr_proj_kernel(
    const float* __restrict__ x,
    const float* __restrict__ Wq, const float* __restrict__ bq,
    const float* __restrict__ Wk, const float* __restrict__ bk,
    const float* __restrict__ Wv, const float* __restrict__ bv)
{
    __shared__ float xs[64 * PR_INDIM];
    __shared__ float ws[64 * 132];

    const int t  = threadIdx.x;
    const int rb = blockIdx.x * 64;
    const int tr = t >> 4;
    const int tc = t & 15;

    {
        const float4* xg  = (const float4*)(x + (size_t)rb * PR_INDIM);
        float4*       xs4 = (float4*)xs;
#pragma unroll
        for (int i = 0; i < 16; i++) xs4[t + i * 256] = xg[t + i * 256];
    }

    const float* Wm[3] = {Wq, Wk, Wv};
    const float* bm[3] = {bq, bk, bv};

#pragma unroll 1
    for (int m = 0; m < 3; m++) {
        float acc[4][8];
#pragma unroll
        for (int c = 0; c < 8; c++) {
            float b = bm[m][tc + 16 * c];
#pragma unroll
            for (int i = 0; i < 4; i++) acc[i][c] = b;
        }

        for (int kb = 0; kb < PR_INDIM; kb += 64) {
            __syncthreads();
            {
                const float4* wg  = (const float4*)(Wm[m] + (size_t)kb * PR_D);
                float4*       ws4 = (float4*)ws;
#pragma unroll
                for (int i = 0; i < 8; i++) ws4[t + i * 256] = wg[t + i * 256];
            }
            __syncthreads();
#pragma unroll 4
            for (int k = 0; k < 64; k++) {
                float xv[4];
#pragma unroll
                for (int i = 0; i < 4; i++)
                    xv[i] = xs[(4 * tr + i) * PR_INDIM + kb + k];
                float wv[8];
#pragma unroll
                for (int c = 0; c < 8; c++)
                    wv[c] = ws[k * PR_D + tc + 16 * c];
#pragma unroll
                for (int i = 0; i < 4; i++)
#pragma unroll
                    for (int c = 0; c < 8; c++)
                        acc[i][c] = fmaf(xv[i], wv[c], acc[i][c]);
            }
        }

        __syncthreads();
#pragma unroll
        for (int i = 0; i < 4; i++)
#pragma unroll
            for (int c = 0; c < 8; c++)
                ws[(4 * tr + i) * 132 + tc + 16 * c] = acc[i][c];
        __syncthreads();

        if (m < 2) {
            __half* Dh = (m == 0) ? g_Qhi : g_Khi;
            __half* Dl = (m == 0) ? g_Qlo : g_Klo;
            const int r  = t >> 2;
            const int cb = (t & 3) * 32;
            uint32_t hi[16], lo[16];
#pragma unroll
            for (int j = 0; j < 16; j++)
                split2h(ws[r * 132 + cb + 2 * j], ws[r * 132 + cb + 2 * j + 1], hi[j], lo[j]);
            uint4* dh = (uint4*)(Dh + (size_t)(rb + r) * PR_D + cb);
            uint4* dl = (uint4*)(Dl + (size_t)(rb + r) * PR_D + cb);
#pragma unroll
            for (int q = 0; q < 4; q++) {
                dh[q] = make_uint4(hi[4*q], hi[4*q+1], hi[4*q+2], hi[4*q+3]);
                dl[q] = make_uint4(lo[4*q], lo[4*q+1], lo[4*q+2], lo[4*q+3]);
            }
        } else {
            // V: transpose to [d][n], single fp16
            const int d    = t >> 1;
            const int half = t & 1;
            uint32_t hv[16];
#pragma unroll
            for (int j = 0; j < 16; j++) {
                int k0 = 32 * half + 2 * j;
                hv[j] = pack_f16x2(ws[k0 * 132 + d], ws[(k0 + 1) * 132 + d]);
            }
            uint4* dv = (uint4*)(g_VTh + (size_t)d * PR_N + rb + 32 * half);
#pragma unroll
            for (int q = 0; q < 4; q++)
                dv[q] = make_uint4(hv[4*q], hv[4*q+1], hv[4*q+2], hv[4*q+3]);
        }
        __syncthreads();
    }
}

// ---------------------------------------------------------------------------
// Kernel 2: HMMA flash attention, softmax(tt) overlapped with PV(tt-1).
//   S  = Q K^T : 3-pass split fp16
//   softmax    : running max, rescale only when max increases; exp/pack of
//                tile tt interleaved with the PV MMAs of tile tt-1
//   O += P V   : single-pass fp16, deferred one tile (double-buffered pp)
// 4 smem buffers, prefetch depth 2.  grid=128 x 256; warp w: rows [16w,16w+16).
// ---------------------------------------------------------------------------
#define KROW   272                 // K row bytes (128 fp16 + pad)
#define VROW   144                 // VT row bytes (64 fp16 + pad)
#define OFF_KH 0
#define OFF_KL 17408
#define OFF_VH 34816
#define ST_BYTES 53248
#define SM_BYTES (4 * ST_BYTES)    // 212992
#define NT (PR_N / 64)             // 256 subtiles (even)

__device__ __forceinline__ void load_stage(uint32_t dst, int kb)
{
    const int t = threadIdx.x;
#pragma unroll
    for (int i = 0; i < 4; i++) {
        int cid = t + i * 256;               // 1024: 64 rows x 16 chunks
        int r = cid >> 4, c = cid & 15;
        cp16(dst + OFF_KH + r * KROW + c * 16, g_Khi + (size_t)(kb + r) * PR_D + c * 8);
        cp16(dst + OFF_KL + r * KROW + c * 16, g_Klo + (size_t)(kb + r) * PR_D + c * 8);
    }
#pragma unroll
    for (int i = 0; i < 4; i++) {
        int cid = t + i * 256;               // 1024: 128 rows x 8 chunks
        int r = cid >> 3, c = cid & 7;
        cp16(dst + OFF_VH + r * VROW + c * 16, g_VTh + (size_t)r * PR_N + kb + c * 8);
    }
}

// One pipelined tile: S(tt) + softmax(tt) interleaved with PV(tt-1).
// ppU = P fragments of tile tt-1 (consumed), ppM = P of tile tt (produced).
__device__ __forceinline__ void attn_tile(
    int tt, uint32_t sb, uint32_t bKoff, uint32_t bVoff,
    const uint32_t (&qh)[8][4], const uint32_t (&ql)[8][4],
    uint32_t (&ppU)[16], uint32_t (&ppM)[16],
    float (&o)[16][4], float& lsum0, float& lsum1, float& M0, float& M1)
{
    const uint32_t pc  = sb + (uint32_t)(tt & 3) * ST_BYTES;
    const uint32_t pv  = sb + (uint32_t)((tt - 1) & 3) * ST_BYTES + OFF_VH + bVoff;
    const uint32_t bKh = pc + OFF_KH + bKoff;
    const uint32_t bKl = pc + OFF_KL + bKoff;

    // ---- S = Q K^T (qh*kh + ql*kh + qh*kl) ----
    float s[8][4];
#pragma unroll
    for (int i = 0; i < 8; i++)
#pragma unroll
        for (int j = 0; j < 4; j++) s[i][j] = 0.0f;

#pragma unroll
    for (int kc = 0; kc < 8; kc++) {
        uint32_t bh[4][4], bl[4][4];
#pragma unroll
        for (int jn = 0; jn < 4; jn++) {
            ldmx4(bh[jn], bKh + jn * (16 * KROW) + kc * 32);
            ldmx4(bl[jn], bKl + jn * (16 * KROW) + kc * 32);
        }
#pragma unroll
        for (int jn = 0; jn < 4; jn++) {
            mma16816h(s[2 * jn],     qh[kc], &bh[jn][0]);
            mma16816h(s[2 * jn + 1], qh[kc], &bh[jn][2]);
        }
#pragma unroll
        for (int jn = 0; jn < 4; jn++) {
            mma16816h(s[2 * jn],     ql[kc], &bh[jn][0]);
            mma16816h(s[2 * jn + 1], ql[kc], &bh[jn][2]);
        }
#pragma unroll
        for (int jn = 0; jn < 4; jn++) {
            mma16816h(s[2 * jn],     qh[kc], &bl[jn][0]);
            mma16816h(s[2 * jn + 1], qh[kc], &bl[jn][2]);
        }
    }

    // ---- local max ----
    float m0 = s[0][0], m1 = s[0][2];
#pragma unroll
    for (int jt = 0; jt < 8; jt++) {
        m0 = fmaxf(m0, fmaxf(s[jt][0], s[jt][1]));
        m1 = fmaxf(m1, fmaxf(s[jt][2], s[jt][3]));
    }

    // ---- PV(tt-1) groups of 4 n-steps, interleaved with softmax scalar work
    uint32_t v[2][4];
    ldmx4(v[0], pv);

#define PV4(g)                                                                 \
    {                                                                          \
        _Pragma("unroll")                                                      \
        for (int u = 0; u < 4; u++) {                                          \
            const int idx = 4 * (g) + u;                                       \
            const int cur = idx & 1, nxt = cur ^ 1;                            \
            if (idx < 31) {                                                    \
                const int i2 = idx + 1, kc2 = i2 >> 3, dn2 = i2 & 7;           \
                ldmx4(v[nxt], pv + dn2 * (16 * VROW) + kc2 * 32);              \
            }                                                                  \
            const int kc = idx >> 3, dn = idx & 7;                             \
            mma16816h(o[2 * dn],     &ppU[4 * kc], &v[cur][0]);                \
            mma16816h(o[2 * dn + 1], &ppU[4 * kc], &v[cur][2]);                \
        }                                                                      \
    }

#define EXPG(j)                                                                \
    {                                                                          \
        float e0 = ex2f(fmaf(s[j][0], LOG2E, -b0));                            \
        float e1 = ex2f(fmaf(s[j][1], LOG2E, -b0));                            \
        float e2 = ex2f(fmaf(s[j][2], LOG2E, -b1));                            \
        float e3 = ex2f(fmaf(s[j][3], LOG2E, -b1));                            \
        ts0 += e0 + e1;                                                        \
        ts1 += e2 + e3;                                                        \
        ppM[2 * (j)]     = pack_f16x2(e0, e1);                                 \
        ppM[2 * (j) + 1] = pack_f16x2(e2, e3);                                 \
    }

    PV4(0)
    PV4(1)

    // shuffle-reduce max across the 4 lanes per row (hidden behind PV MMAs)
    m0 = fmaxf(m0, __shfl_xor_sync(0xffffffffu, m0, 1));
    m0 = fmaxf(m0, __shfl_xor_sync(0xffffffffu, m0, 2));
    m1 = fmaxf(m1, __shfl_xor_sync(0xffffffffu, m1, 1));
    m1 = fmaxf(m1, __shfl_xor_sync(0xffffffffu, m1, 2));

    const bool need = (m0 > M0) || (m1 > M1);
    float sc0 = 1.0f, sc1 = 1.0f;
    if (need) {
        const float M0n = fmaxf(M0, m0), M1n = fmaxf(M1, m1);
        sc0 = ex2f((M0 - M0n) * LOG2E);
        sc1 = ex2f((M1 - M1n) * LOG2E);
        M0 = M0n; M1 = M1n;
        lsum0 *= sc0;
        lsum1 *= sc1;
    }
    const float b0 = M0 * LOG2E, b1 = M1 * LOG2E;
    float ts0 = 0.0f, ts1 = 0.0f;

    EXPG(0) PV4(2)
    EXPG(1) PV4(3)
    EXPG(2) PV4(4)
    EXPG(3) PV4(5)
    EXPG(4) PV4(6)
    EXPG(5) PV4(7)
    EXPG(6)
    EXPG(7)

    // o rescale after PV(tt-1) fully accumulated (pre-rescale scale) — this
    // brings o to the tile-tt max convention before PV(tt) next iteration.
    if (need) {
#pragma unroll
        for (int dt = 0; dt < 16; dt++) {
            o[dt][0] *= sc0; o[dt][1] *= sc0;
            o[dt][2] *= sc1; o[dt][3] *= sc1;
        }
    }
    lsum0 += ts0;
    lsum1 += ts1;
#undef PV4
#undef EXPG
}

__global__ void __launch_bounds__(256, 1) pr_attn_mma(float* __restrict__ out)
{
    extern __shared__ char sm[];
    const uint32_t sb = smem_u32(sm);

    const int t    = threadIdx.x;
    const int w    = t >> 5;
    const int lane = t & 31;
    const int qb   = blockIdx.x * 128;

    const uint32_t aRow = (uint32_t)(16 * w + (lane & 15));
    const uint32_t aCol = (uint32_t)(lane >> 4);
    const uint32_t bRow = (uint32_t)((lane & 7) + 8 * (lane >> 4));
    const uint32_t bCol = (uint32_t)((lane >> 3) & 1);
    const uint32_t bKoff = bRow * KROW + bCol * 16;
    const uint32_t bVoff = bRow * VROW + bCol * 16;

    // ---- stage Q and grab fragments ----
    {
#pragma unroll
        for (int i = 0; i < 8; i++) {
            int cid = t + i * 256;
            int r = cid >> 4, c = cid & 15;
            cp16(sb + r * KROW + c * 16,         g_Qhi + (size_t)(qb + r) * PR_D + c * 8);
            cp16(sb + 34816 + r * KROW + c * 16, g_Qlo + (size_t)(qb + r) * PR_D + c * 8);
        }
        cp_commit();
        cp_wait0();
        __syncthreads();
    }
    uint32_t qh[8][4], ql[8][4];
    {
        const uint32_t aQ = sb + aRow * KROW + aCol * 16;
#pragma unroll
        for (int kc = 0; kc < 8; kc++) {
            ldmx4(qh[kc], aQ + kc * 32);
            ldmx4(ql[kc], aQ + 34816 + kc * 32);
        }
    }
    __syncthreads();

    float o[16][4];
#pragma unroll
    for (int i = 0; i < 16; i++)
#pragma unroll
        for (int j = 0; j < 4; j++) o[i][j] = 0.0f;
    float lsum0 = 0.0f, lsum1 = 0.0f;
    float M0, M1;
    uint32_t ppA[16], ppB[16];

    // prefetch tiles 0,1
    load_stage(sb + 0 * ST_BYTES, 0);
    cp_commit();
    load_stage(sb + 1 * ST_BYTES, 64);
    cp_commit();

    // ---- prologue: tile 0 (S + softmax -> ppA, no PV yet) ----
    {
        load_stage(sb + 2 * ST_BYTES, 128);
        cp_commit();
        cp_wait2();
        __syncthreads();

        const uint32_t bKh = sb + OFF_KH + bKoff;
        const uint32_t bKl = sb + OFF_KL + bKoff;

        float s[8][4];
#pragma unroll
        for (int i = 0; i < 8; i++)
#pragma unroll
            for (int j = 0; j < 4; j++) s[i][j] = 0.0f;
#pragma unroll
        for (int kc = 0; kc < 8; kc++) {
            uint32_t bh[4][4], bl[4][4];
#pragma unroll
            for (int jn = 0; jn < 4; jn++) {
                ldmx4(bh[jn], bKh + jn * (16 * KROW) + kc * 32);
                ldmx4(bl[jn], bKl + jn * (16 * KROW) + kc * 32);
            }
#pragma unroll
            for (int jn = 0; jn < 4; jn++) {
                mma16816h(s[2 * jn],     qh[kc], &bh[jn][0]);
                mma16816h(s[2 * jn + 1], qh[kc], &bh[jn][2]);
            }
#pragma unroll
            for (int jn = 0; jn < 4; jn++) {
                mma16816h(s[2 * jn],     ql[kc], &bh[jn][0]);
                mma16816h(s[2 * jn + 1], ql[kc], &bh[jn][2]);
            }
#pragma unroll
            for (int jn = 0; jn < 4; jn++) {
                mma16816h(s[2 * jn],     qh[kc], &bl[jn][0]);
                mma16816h(s[2 * jn + 1], qh[kc], &bl[jn][2]);
            }
        }

        float m0 = s[0][0], m1 = s[0][2];
#pragma unroll
        for (int jt = 0; jt < 8; jt++) {
            m0 = fmaxf(m0, fmaxf(s[jt][0], s[jt][1]));
            m1 = fmaxf(m1, fmaxf(s[jt][2], s[jt][3]));
        }
        m0 = fmaxf(m0, __shfl_xor_sync(0xffffffffu, m0, 1));
        m0 = fmaxf(m0, __shfl_xor_sync(0xffffffffu, m0, 2));
        m1 = fmaxf(m1, __shfl_xor_sync(0xffffffffu, m1, 1));
        m1 = fmaxf(m1, __shfl_xor_sync(0xffffffffu, m1, 2));
        M0 = m0; M1 = m1;
        const float b0 = M0 * LOG2E, b1 = M1 * LOG2E;
#pragma unroll
        for (int jt = 0; jt < 8; jt++) {
            float e0 = ex2f(fmaf(s[jt][0], LOG2E, -b0));
            float e1 = ex2f(fmaf(s[jt][1], LOG2E, -b0));
            float e2 = ex2f(fmaf(s[jt][2], LOG2E, -b1));
            float e3 = ex2f(fmaf(s[jt][3], LOG2E, -b1));
            lsum0 += e0 + e1;
            lsum1 += e2 + e3;
            ppA[2 * jt]     = pack_f16x2(e0, e1);
            ppA[2 * jt + 1] = pack_f16x2(e2, e3);
        }
    }

    // ---- main pipelined loop: tiles 1..NT-1 in pairs ----
#pragma unroll 1
    for (int tt = 1; tt < NT; tt += 2) {
        __syncthreads();
        if (tt + 2 < NT) load_stage(sb + (uint32_t)((tt + 2) & 3) * ST_BYTES, (tt + 2) * 64);
        cp_commit();
        cp_wait2();
        __syncthreads();
        attn_tile(tt, sb, bKoff, bVoff, qh, ql, ppA, ppB, o, lsum0, lsum1, M0, M1);

        if (tt + 1 < NT) {
            __syncthreads();
            if (tt + 3 < NT) load_stage(sb + (uint32_t)((tt + 3) & 3) * ST_BYTES, (tt + 3) * 64);
            cp_commit();
            cp_wait2();
            __syncthreads();
            attn_tile(tt + 1, sb, bKoff, bVoff, qh, ql, ppB, ppA, o, lsum0, lsum1, M0, M1);
        }
    }

    // ---- epilogue: PV for the last tile (NT-1, odd -> pp in ppB) ----
    {
        const uint32_t pv = sb + (uint32_t)((NT - 1) & 3) * ST_BYTES + OFF_VH + bVoff;
        uint32_t v[2][4];
        ldmx4(v[0], pv);
#pragma unroll
        for (int idx = 0; idx < 32; idx++) {
            const int cur = idx & 1, nxt = cur ^ 1;
            if (idx < 31) {
                const int i2 = idx + 1, kc2 = i2 >> 3, dn2 = i2 & 7;
                ldmx4(v[nxt], pv + dn2 * (16 * VROW) + kc2 * 32);
            }
            const int kc = idx >> 3, dn = idx & 7;
            mma16816h(o[2 * dn],     &ppB[4 * kc], &v[cur][0]);
            mma16816h(o[2 * dn + 1], &ppB[4 * kc], &v[cur][2]);
        }
    }

    // ---- reduce row sums over the 4 lanes sharing each row ----
    lsum0 += __shfl_xor_sync(0xffffffffu, lsum0, 1);
    lsum0 += __shfl_xor_sync(0xffffffffu, lsum0, 2);
    lsum1 += __shfl_xor_sync(0xffffffffu, lsum1, 1);
    lsum1 += __shfl_xor_sync(0xffffffffu, lsum1, 2);
    const float inv0 = 1.0f / lsum0;
    const float inv1 = 1.0f / lsum1;

    const int r0 = qb + 16 * w + (lane >> 2);
    const int cb = 2 * (lane & 3);
#pragma unroll
    for (int dt = 0; dt < 16; dt++) {
        float2 v0 = make_float2(o[dt][0] * inv0, o[dt][1] * inv0);
        float2 v1 = make_float2(o[dt][2] * inv1, o[dt][3] * inv1);
        *(float2*)(out + (size_t)r0 * PR_D + 8 * dt + cb)       = v0;
        *(float2*)(out + (size_t)(r0 + 8) * PR_D + 8 * dt + cb) = v1;
    }
}

// ---------------------------------------------------------------------------
extern "C" void kernel_launch(void* const* d_in, const int* in_sizes, int n_in,
                              void* d_out, int out_size)
{
    const float* x  = (const float*)d_in[0];
    const float* Wq = (const float*)d_in[1];
    const float* bq = (const float*)d_in[2];
    const float* Wk = (const float*)d_in[3];
    const float* bk = (const float*)d_in[4];
    const float* Wv = (const float*)d_in[5];
    const float* bv = (const float*)d_in[6];
    float* out = (float*)d_out;

    pr_proj_kernel<<<PR_N / 64, 256>>>(x, Wq, bq, Wk, bk, Wv, bv);

    cudaFuncSetAttribute(pr_attn_mma,
                         cudaFuncAttributeMaxDynamicSharedMemorySize, SM_BYTES);
    pr_attn_mma<<<PR_N / 128, 256, SM_BYTES>>>(out);
}

// round 9
// speedup vs baseline: 1.3090x; 1.3090x over previous
#include <cuda_runtime.h>
#include <cuda_fp16.h>
#include <cstdint>
#include <cstddef>

#define PR_N      16384
#define PR_INDIM  256
#define PR_D      128
#define LOG2E     1.4426950408889634f

// ---------------- scratch: Q split (hi+lo fp16), K and V single fp16 --------
__device__ __align__(16) __half g_Qhi[PR_N * PR_D];
__device__ __align__(16) __half g_Qlo[PR_N * PR_D];
__device__ __align__(16) __half g_Kh [PR_N * PR_D];
__device__ __align__(16) __half g_VTh[PR_D * PR_N];   // V transposed [d][n]

// ---------------- helpers ---------------------------------------------------
__device__ __forceinline__ uint32_t smem_u32(const void* p) {
    uint32_t a;
    asm("{ .reg .u64 t; cvta.to.shared.u64 t, %1; cvt.u32.u64 %0, t; }"
        : "=r"(a) : "l"(p));
    return a;
}
__device__ __forceinline__ float ex2f(float x) {   // MUFU.EX2
    float r;
    asm("ex2.approx.ftz.f32 %0, %1;" : "=f"(r) : "f"(x));
    return r;
}
__device__ __forceinline__ uint32_t pack_f16x2(float a, float b) {
    uint32_t r;
    asm("cvt.rn.f16x2.f32 %0, %1, %2;" : "=r"(r) : "f"(b), "f"(a));
    return r;
}
__device__ __forceinline__ void split2h(float f0, float f1, uint32_t& hi, uint32_t& lo) {
    __half a0 = __float2half_rn(f0), a1 = __float2half_rn(f1);
    hi = ((uint32_t)__half_as_ushort(a1) << 16) | __half_as_ushort(a0);
    lo = pack_f16x2(f0 - __half2float(a0), f1 - __half2float(a1));
}
__device__ __forceinline__ void ldmx4(uint32_t* r, uint32_t addr) {
    asm volatile("ldmatrix.sync.aligned.m8n8.x4.shared.b16 {%0,%1,%2,%3}, [%4];"
                 : "=r"(r[0]), "=r"(r[1]), "=r"(r[2]), "=r"(r[3]) : "r"(addr));
}
__device__ __forceinline__ void mma16816h(float* c, const uint32_t* a,
                                          const uint32_t* b) {
    asm volatile(
        "mma.sync.aligned.m16n8k16.row.col.f32.f16.f16.f32 "
        "{%0,%1,%2,%3}, {%4,%5,%6,%7}, {%8,%9}, {%0,%1,%2,%3};"
        : "+f"(c[0]), "+f"(c[1]), "+f"(c[2]), "+f"(c[3])
        : "r"(a[0]), "r"(a[1]), "r"(a[2]), "r"(a[3]), "r"(b[0]), "r"(b[1]));
}
__device__ __forceinline__ void cp16(uint32_t dst, const void* src) {
    asm volatile("cp.async.cg.shared.global [%0], [%1], 16;"
                 :: "r"(dst), "l"(src) : "memory");
}
__device__ __forceinline__ void cp_commit() {
    asm volatile("cp.async.commit_group;" ::: "memory");
}
__device__ __forceinline__ void cp_wait2() {
    asm volatile("cp.async.wait_group 2;" ::: "memory");
}
__device__ __forceinline__ void cp_wait0() {
    asm volatile("cp.async.wait_group 0;" ::: "memory");
}

// ---------------------------------------------------------------------------
// Kernel 1: QKV projection; Q split fp16 hi/lo, K single fp16, V^T single.
// ---------------------------------------------------------------------------
__global__ void __launch_bounds__(256) pr_proj_kernel(
    const float* __restrict__ x,
    const float* __restrict__ Wq, const float* __restrict__ bq,
    const float* __restrict__ Wk, const float* __restrict__ bk,
    const float* __restrict__ Wv, const float* __restrict__ bv)
{
    __shared__ float xs[64 * PR_INDIM];
    __shared__ float ws[64 * 132];

    const int t  = threadIdx.x;
    const int rb = blockIdx.x * 64;
    const int tr = t >> 4;
    const int tc = t & 15;

    {
        const float4* xg  = (const float4*)(x + (size_t)rb * PR_INDIM);
        float4*       xs4 = (float4*)xs;
#pragma unroll
        for (int i = 0; i < 16; i++) xs4[t + i * 256] = xg[t + i * 256];
    }

    const float* Wm[3] = {Wq, Wk, Wv};
    const float* bm[3] = {bq, bk, bv};

#pragma unroll 1
    for (int m = 0; m < 3; m++) {
        float acc[4][8];
#pragma unroll
        for (int c = 0; c < 8; c++) {
            float b = bm[m][tc + 16 * c];
#pragma unroll
            for (int i = 0; i < 4; i++) acc[i][c] = b;
        }

        for (int kb = 0; kb < PR_INDIM; kb += 64) {
            __syncthreads();
            {
                const float4* wg  = (const float4*)(Wm[m] + (size_t)kb * PR_D);
                float4*       ws4 = (float4*)ws;
#pragma unroll
                for (int i = 0; i < 8; i++) ws4[t + i * 256] = wg[t + i * 256];
            }
            __syncthreads();
#pragma unroll 4
            for (int k = 0; k < 64; k++) {
                float xv[4];
#pragma unroll
                for (int i = 0; i < 4; i++)
                    xv[i] = xs[(4 * tr + i) * PR_INDIM + kb + k];
                float wv[8];
#pragma unroll
                for (int c = 0; c < 8; c++)
                    wv[c] = ws[k * PR_D + tc + 16 * c];
#pragma unroll
                for (int i = 0; i < 4; i++)
#pragma unroll
                    for (int c = 0; c < 8; c++)
                        acc[i][c] = fmaf(xv[i], wv[c], acc[i][c]);
            }
        }

        __syncthreads();
#pragma unroll
        for (int i = 0; i < 4; i++)
#pragma unroll
            for (int c = 0; c < 8; c++)
                ws[(4 * tr + i) * 132 + tc + 16 * c] = acc[i][c];
        __syncthreads();

        if (m == 0) {
            // Q: split hi/lo
            const int r  = t >> 2;
            const int cb = (t & 3) * 32;
            uint32_t hi[16], lo[16];
#pragma unroll
            for (int j = 0; j < 16; j++)
                split2h(ws[r * 132 + cb + 2 * j], ws[r * 132 + cb + 2 * j + 1], hi[j], lo[j]);
            uint4* dh = (uint4*)(g_Qhi + (size_t)(rb + r) * PR_D + cb);
            uint4* dl = (uint4*)(g_Qlo + (size_t)(rb + r) * PR_D + cb);
#pragma unroll
            for (int q = 0; q < 4; q++) {
                dh[q] = make_uint4(hi[4*q], hi[4*q+1], hi[4*q+2], hi[4*q+3]);
                dl[q] = make_uint4(lo[4*q], lo[4*q+1], lo[4*q+2], lo[4*q+3]);
            }
        } else if (m == 1) {
            // K: single fp16
            const int r  = t >> 2;
            const int cb = (t & 3) * 32;
            uint32_t hv[16];
#pragma unroll
            for (int j = 0; j < 16; j++)
                hv[j] = pack_f16x2(ws[r * 132 + cb + 2 * j], ws[r * 132 + cb + 2 * j + 1]);
            uint4* dv = (uint4*)(g_Kh + (size_t)(rb + r) * PR_D + cb);
#pragma unroll
            for (int q = 0; q < 4; q++)
                dv[q] = make_uint4(hv[4*q], hv[4*q+1], hv[4*q+2], hv[4*q+3]);
        } else {
            // V: transpose to [d][n], single fp16
            const int d    = t >> 1;
            const int half = t & 1;
            uint32_t hv[16];
#pragma unroll
            for (int j = 0; j < 16; j++) {
                int k0 = 32 * half + 2 * j;
                hv[j] = pack_f16x2(ws[k0 * 132 + d], ws[(k0 + 1) * 132 + d]);
            }
            uint4* dv = (uint4*)(g_VTh + (size_t)d * PR_N + rb + 32 * half);
#pragma unroll
            for (int q = 0; q < 4; q++)
                dv[q] = make_uint4(hv[4*q], hv[4*q+1], hv[4*q+2], hv[4*q+3]);
        }
        __syncthreads();
    }
}

// ---------------------------------------------------------------------------
// Kernel 2: HMMA flash attention.
//   S  = Q K^T : 2-pass (qh*k + ql*k), K single fp16 (q exact, k ~2^-12)
//   softmax    : running max, rescale only when max increases
//   O += P V   : single-pass fp16
// 4-buffer cp.async pipeline over 64-key subtiles, Q frags register-resident.
// grid = 128 CTAs x 256 thr; warp w owns q rows [16w, 16w+16).
// ---------------------------------------------------------------------------
#define KROW   272                 // K row bytes (128 fp16 + pad)
#define VROW   144                 // VT row bytes (64 fp16 + pad)
#define OFF_K  0
#define OFF_V  17408               // 64*272
#define ST_BYTES 35840             // 17408 + 128*144
#define SM_BYTES (4 * ST_BYTES)    // 143360
#define NT (PR_N / 64)             // 256 subtiles

__device__ __forceinline__ void load_stage(uint32_t dst, int kb)
{
    const int t = threadIdx.x;
#pragma unroll
    for (int i = 0; i < 4; i++) {
        int cid = t + i * 256;               // 1024: 64 rows x 16 chunks
        int r = cid >> 4, c = cid & 15;
        cp16(dst + OFF_K + r * KROW + c * 16, g_Kh + (size_t)(kb + r) * PR_D + c * 8);
    }
#pragma unroll
    for (int i = 0; i < 4; i++) {
        int cid = t + i * 256;               // 1024: 128 rows x 8 chunks
        int r = cid >> 3, c = cid & 7;
        cp16(dst + OFF_V + r * VROW + c * 16, g_VTh + (size_t)r * PR_N + kb + c * 8);
    }
}

__global__ void __launch_bounds__(256, 1) pr_attn_mma(float* __restrict__ out)
{
    extern __shared__ char sm[];
    const uint32_t sb = smem_u32(sm);

    const int t    = threadIdx.x;
    const int w    = t >> 5;
    const int lane = t & 31;
    const int qb   = blockIdx.x * 128;

    const uint32_t aRow = (uint32_t)(16 * w + (lane & 15));
    const uint32_t aCol = (uint32_t)(lane >> 4);
    const uint32_t bRow = (uint32_t)((lane & 7) + 8 * (lane >> 4));
    const uint32_t bCol = (uint32_t)((lane >> 3) & 1);
    const uint32_t bKoff = bRow * KROW + bCol * 16;
    const uint32_t bVoff = bRow * VROW + bCol * 16;

    // ---- stage Q (hi at sb, lo at sb+34816) and grab fragments ----
    {
#pragma unroll
        for (int i = 0; i < 8; i++) {
            int cid = t + i * 256;
            int r = cid >> 4, c = cid & 15;
            cp16(sb + r * KROW + c * 16,         g_Qhi + (size_t)(qb + r) * PR_D + c * 8);
            cp16(sb + 34816 + r * KROW + c * 16, g_Qlo + (size_t)(qb + r) * PR_D + c * 8);
        }
        cp_commit();
        cp_wait0();
        __syncthreads();
    }
    uint32_t qh[8][4], ql[8][4];
    {
        const uint32_t aQ = sb + aRow * KROW + aCol * 16;
#pragma unroll
        for (int kc = 0; kc < 8; kc++) {
            ldmx4(qh[kc], aQ + kc * 32);
            ldmx4(ql[kc], aQ + 34816 + kc * 32);
        }
    }
    __syncthreads();

    float o[16][4];
#pragma unroll
    for (int i = 0; i < 16; i++)
#pragma unroll
        for (int j = 0; j < 4; j++) o[i][j] = 0.0f;
    float lsum0 = 0.0f, lsum1 = 0.0f;
    float M0 = -1e30f, M1 = -1e30f;

    // prefetch tiles 0,1,2
    load_stage(sb + 0 * ST_BYTES, 0);
    cp_commit();
    load_stage(sb + 1 * ST_BYTES, 64);
    cp_commit();
    load_stage(sb + 2 * ST_BYTES, 128);
    cp_commit();

    int st_cur = 0, st_pre = 3;
#pragma unroll 1
    for (int tt = 0; tt < NT; tt++) {
        __syncthreads();                 // prefetch target free of readers
        if (tt + 3 < NT) load_stage(sb + st_pre * ST_BYTES, (tt + 3) * 64);
        cp_commit();
        cp_wait2();                      // oldest (tile tt) arrived
        __syncthreads();

        const uint32_t p   = sb + st_cur * ST_BYTES;
        const uint32_t bKh = p + OFF_K + bKoff;
        const uint32_t bVh = p + OFF_V + bVoff;

        // ---- S = Q K^T (qh*k + ql*k), 64 keys ----
        float s[8][4];
#pragma unroll
        for (int i = 0; i < 8; i++)
#pragma unroll
            for (int j = 0; j < 4; j++) s[i][j] = 0.0f;

#pragma unroll
        for (int kc = 0; kc < 8; kc++) {
            uint32_t bh[4][4];
#pragma unroll
            for (int jn = 0; jn < 4; jn++)
                ldmx4(bh[jn], bKh + jn * (16 * KROW) + kc * 32);
            // two waves of 8 independent MMAs (accumulator reuse distance 8)
#pragma unroll
            for (int jn = 0; jn < 4; jn++) {
                mma16816h(s[2 * jn],     qh[kc], &bh[jn][0]);
                mma16816h(s[2 * jn + 1], qh[kc], &bh[jn][2]);
            }
#pragma unroll
            for (int jn = 0; jn < 4; jn++) {
                mma16816h(s[2 * jn],     ql[kc], &bh[jn][0]);
                mma16816h(s[2 * jn + 1], ql[kc], &bh[jn][2]);
            }
        }

        // ---- flash softmax: running max, rescale only on max increase ----
        float m0 = s[0][0], m1 = s[0][2];
#pragma unroll
        for (int jt = 0; jt < 8; jt++) {
            m0 = fmaxf(m0, fmaxf(s[jt][0], s[jt][1]));
            m1 = fmaxf(m1, fmaxf(s[jt][2], s[jt][3]));
        }
        m0 = fmaxf(m0, __shfl_xor_sync(0xffffffffu, m0, 1));
        m0 = fmaxf(m0, __shfl_xor_sync(0xffffffffu, m0, 2));
        m1 = fmaxf(m1, __shfl_xor_sync(0xffffffffu, m1, 1));
        m1 = fmaxf(m1, __shfl_xor_sync(0xffffffffu, m1, 2));

        if (m0 > M0 || m1 > M1) {        // rare after the first few tiles
            const float M0n = fmaxf(M0, m0), M1n = fmaxf(M1, m1);
            const float sc0 = ex2f((M0 - M0n) * LOG2E);
            const float sc1 = ex2f((M1 - M1n) * LOG2E);
            M0 = M0n; M1 = M1n;
            lsum0 *= sc0;
            lsum1 *= sc1;
#pragma unroll
            for (int dt = 0; dt < 16; dt++) {
                o[dt][0] *= sc0; o[dt][1] *= sc0;
                o[dt][2] *= sc1; o[dt][3] *= sc1;
            }
        }
        const float b0 = M0 * LOG2E, b1 = M1 * LOG2E;

        float ts0 = 0.0f, ts1 = 0.0f;
        uint32_t pp[16];
#pragma unroll
        for (int jt = 0; jt < 8; jt++) {
            float e0 = ex2f(fmaf(s[jt][0], LOG2E, -b0));
            float e1 = ex2f(fmaf(s[jt][1], LOG2E, -b0));
            float e2 = ex2f(fmaf(s[jt][2], LOG2E, -b1));
            float e3 = ex2f(fmaf(s[jt][3], LOG2E, -b1));
            ts0 += e0 + e1;
            ts1 += e2 + e3;
            pp[2 * jt]     = pack_f16x2(e0, e1);
            pp[2 * jt + 1] = pack_f16x2(e2, e3);
        }
        lsum0 += ts0;
        lsum1 += ts1;

        // ---- O += P V (single-pass fp16), k = 64 keys ----
        uint32_t v[2][4];
        ldmx4(v[0], bVh);
#pragma unroll
        for (int idx = 0; idx < 32; idx++) {
            const int cur = idx & 1, nxt = cur ^ 1;
            if (idx < 31) {
                const int kc2 = (idx + 1) >> 3, dn2 = (idx + 1) & 7;
                ldmx4(v[nxt], bVh + dn2 * (16 * VROW) + kc2 * 32);
            }
            const int kc = idx >> 3, dn = idx & 7;
            mma16816h(o[2 * dn],     &pp[4 * kc], &v[cur][0]);
            mma16816h(o[2 * dn + 1], &pp[4 * kc], &v[cur][2]);
        }

        st_cur = (st_cur + 1) & 3;
        st_pre = (st_pre + 1) & 3;
    }

    // ---- reduce row sums over the 4 lanes sharing each row ----
    lsum0 += __shfl_xor_sync(0xffffffffu, lsum0, 1);
    lsum0 += __shfl_xor_sync(0xffffffffu, lsum0, 2);
    lsum1 += __shfl_xor_sync(0xffffffffu, lsum1, 1);
    lsum1 += __shfl_xor_sync(0xffffffffu, lsum1, 2);
    const float inv0 = 1.0f / lsum0;
    const float inv1 = 1.0f / lsum1;

    const int r0 = qb + 16 * w + (lane >> 2);
    const int cb = 2 * (lane & 3);
#pragma unroll
    for (int dt = 0; dt < 16; dt++) {
        float2 v0 = make_float2(o[dt][0] * inv0, o[dt][1] * inv0);
        float2 v1 = make_float2(o[dt][2] * inv1, o[dt][3] * inv1);
        *(float2*)(out + (size_t)r0 * PR_D + 8 * dt + cb)       = v0;
        *(float2*)(out + (size_t)(r0 + 8) * PR_D + 8 * dt + cb) = v1;
    }
}

// ---------------------------------------------------------------------------
extern "C" void kernel_launch(void* const* d_in, const int* in_sizes, int n_in,
                              void* d_out, int out_size)
{
    const float* x  = (const float*)d_in[0];
    const float* Wq = (const float*)d_in[1];
    const float* bq = (const float*)d_in[2];
    const float* Wk = (const float*)d_in[3];
    const float* bk = (const float*)d_in[4];
    const float* Wv = (const float*)d_in[5];
    const float* bv = (const float*)d_in[6];
    float* out = (float*)d_out;

    pr_proj_kernel<<<PR_N / 64, 256>>>(x, Wq, bq, Wk, bk, Wv, bv);

    cudaFuncSetAttribute(pr_attn_mma,
                         cudaFuncAttributeMaxDynamicSharedMemorySize, SM_BYTES);
    pr_attn_mma<<<PR_N / 128, 256, SM_BYTES>>>(out);
}

// round 11
// speedup vs baseline: 1.4500x; 1.1077x over previous
#include <cuda_runtime.h>
#include <cuda_fp16.h>
#include <cstdint>
#include <cstddef>

#define PR_N      16384
#define PR_INDIM  256
#define PR_D      128
#define LOG2E     1.4426950408889634f

// ---------------- scratch ---------------------------------------------------
__device__ __align__(16) __half g_Qhi[PR_N * PR_D];
__device__ __align__(16) __half g_Qlo[PR_N * PR_D];
__device__ __align__(16) __half g_Kh [PR_N * PR_D];
__device__ __align__(16) __half g_VTh[PR_D * PR_N];       // V^T [d][n]
__device__ __align__(16) __half g_xh [PR_N * PR_INDIM];   // x split hi
__device__ __align__(16) __half g_xl [PR_N * PR_INDIM];   // x split lo
__device__ __align__(16) __half g_WTh[3 * PR_D * PR_INDIM]; // W^T split hi [m][out][in]
__device__ __align__(16) __half g_WTl[3 * PR_D * PR_INDIM];

// ---------------- helpers ---------------------------------------------------
__device__ __forceinline__ uint32_t smem_u32(const void* p) {
    uint32_t a;
    asm("{ .reg .u64 t; cvta.to.shared.u64 t, %1; cvt.u32.u64 %0, t; }"
        : "=r"(a) : "l"(p));
    return a;
}
__device__ __forceinline__ float ex2f(float x) {
    float r;
    asm("ex2.approx.ftz.f32 %0, %1;" : "=f"(r) : "f"(x));
    return r;
}
__device__ __forceinline__ uint32_t pack_f16x2(float a, float b) {
    uint32_t r;
    asm("cvt.rn.f16x2.f32 %0, %1, %2;" : "=r"(r) : "f"(b), "f"(a));
    return r;
}
__device__ __forceinline__ void split2h(float f0, float f1, uint32_t& hi, uint32_t& lo) {
    __half a0 = __float2half_rn(f0), a1 = __float2half_rn(f1);
    hi = ((uint32_t)__half_as_ushort(a1) << 16) | __half_as_ushort(a0);
    lo = pack_f16x2(f0 - __half2float(a0), f1 - __half2float(a1));
}
__device__ __forceinline__ void ldmx4(uint32_t* r, uint32_t addr) {
    asm volatile("ldmatrix.sync.aligned.m8n8.x4.shared.b16 {%0,%1,%2,%3}, [%4];"
                 : "=r"(r[0]), "=r"(r[1]), "=r"(r[2]), "=r"(r[3]) : "r"(addr));
}
__device__ __forceinline__ void mma16816h(float* c, const uint32_t* a,
                                          const uint32_t* b) {
    asm volatile(
        "mma.sync.aligned.m16n8k16.row.col.f32.f16.f16.f32 "
        "{%0,%1,%2,%3}, {%4,%5,%6,%7}, {%8,%9}, {%0,%1,%2,%3};"
        : "+f"(c[0]), "+f"(c[1]), "+f"(c[2]), "+f"(c[3])
        : "r"(a[0]), "r"(a[1]), "r"(a[2]), "r"(a[3]), "r"(b[0]), "r"(b[1]));
}
__device__ __forceinline__ void cp16(uint32_t dst, const void* src) {
    asm volatile("cp.async.cg.shared.global [%0], [%1], 16;"
                 :: "r"(dst), "l"(src) : "memory");
}
__device__ __forceinline__ void cp_commit() {
    asm volatile("cp.async.commit_group;" ::: "memory");
}
__device__ __forceinline__ void cp_wait2() {
    asm volatile("cp.async.wait_group 2;" ::: "memory");
}
__device__ __forceinline__ void cp_wait0() {
    asm volatile("cp.async.wait_group 0;" ::: "memory");
}

// ---------------------------------------------------------------------------
// Kernel 0: convert x -> fp16 hi/lo; W -> W^T fp16 hi/lo.  grid=2096 x 256.
// ---------------------------------------------------------------------------
__global__ void __launch_bounds__(256) pr_convert(
    const float* __restrict__ x,
    const float* __restrict__ Wq, const float* __restrict__ Wk,
    const float* __restrict__ Wv)
{
    const int bid = blockIdx.x, t = threadIdx.x;
    if (bid < 2048) {
        size_t e0 = ((size_t)bid * 256 + t) * 8;
        float4 f0 = *(const float4*)(x + e0);
        float4 f1 = *(const float4*)(x + e0 + 4);
        uint32_t h[4], l[4];
        split2h(f0.x, f0.y, h[0], l[0]);
        split2h(f0.z, f0.w, h[1], l[1]);
        split2h(f1.x, f1.y, h[2], l[2]);
        split2h(f1.z, f1.w, h[3], l[3]);
        *(uint4*)(g_xh + e0) = make_uint4(h[0], h[1], h[2], h[3]);
        *(uint4*)(g_xl + e0) = make_uint4(l[0], l[1], l[2], l[3]);
    } else {
        int idx = (bid - 2048) * 256 + t;   // 12288 total: [m][d][k-chunk of 8]
        int m   = idx >> 12;                // / 4096
        int rem = idx & 4095;
        int d   = rem >> 5;
        int k0  = (rem & 31) * 8;
        const float* W = (m == 0) ? Wq : ((m == 1) ? Wk : Wv);
        uint32_t h[4], l[4];
#pragma unroll
        for (int i = 0; i < 4; i++) {
            float a = W[(size_t)(k0 + 2 * i) * PR_D + d];
            float b = W[(size_t)(k0 + 2 * i + 1) * PR_D + d];
            split2h(a, b, h[i], l[i]);
        }
        size_t o = ((size_t)m * PR_D + d) * PR_INDIM + k0;
        *(uint4*)(g_WTh + o) = make_uint4(h[0], h[1], h[2], h[3]);
        *(uint4*)(g_WTl + o) = make_uint4(l[0], l[1], l[2], l[3]);
    }
}

// ---------------------------------------------------------------------------
// Kernel 1: HMMA projection, 3-pass split fp16 (xh*Wh + xl*Wh + xh*Wl).
// grid=128 x 256; CTA: 128 rows.  xh frags in regs; xl + WT hi/lo in smem.
// ---------------------------------------------------------------------------
#define XROW    528                  // 256 fp16 + 16B pad
#define SM_X    0
#define SM_WH   67584                // 128*528
#define SM_WL   135168
#define PROJ_SM 202752

__global__ void __launch_bounds__(256, 1) pr_proj_mma(
    const float* __restrict__ bq, const float* __restrict__ bk,
    const float* __restrict__ bv)
{
    extern __shared__ char sm[];
    const uint32_t sb = smem_u32(sm);

    const int t    = threadIdx.x;
    const int w    = t >> 5;
    const int lane = t & 31;
    const int qb   = blockIdx.x * 128;

    const uint32_t aoff = (uint32_t)(16 * w + (lane & 15)) * XROW
                        + (uint32_t)(lane >> 4) * 16;
    const uint32_t boff = (uint32_t)((lane & 7) + 8 * (lane >> 4)) * XROW
                        + (uint32_t)((lane >> 3) & 1) * 16;

    // ---- load x-hi, extract A fragments into registers ----
#pragma unroll
    for (int i = 0; i < 16; i++) {
        int cid = t + i * 256;                 // 128 rows x 32 chunks
        int r = cid >> 5, c = cid & 31;
        cp16(sb + SM_X + r * XROW + c * 16, g_xh + (size_t)(qb + r) * PR_INDIM + c * 8);
    }
    cp_commit();
    cp_wait0();
    __syncthreads();

    uint32_t xh[16][4];
#pragma unroll
    for (int kc = 0; kc < 16; kc++)
        ldmx4(xh[kc], sb + SM_X + aoff + kc * 32);
    __syncthreads();

    // ---- load x-lo (overwrites X) + WT(0) hi/lo ----
#pragma unroll
    for (int i = 0; i < 16; i++) {
        int cid = t + i * 256;
        int r = cid >> 5, c = cid & 31;
        cp16(sb + SM_X + r * XROW + c * 16, g_xl + (size_t)(qb + r) * PR_INDIM + c * 8);
        cp16(sb + SM_WH + r * XROW + c * 16, g_WTh + (size_t)r * PR_INDIM + c * 8);
        cp16(sb + SM_WL + r * XROW + c * 16, g_WTl + (size_t)r * PR_INDIM + c * 8);
    }
    cp_commit();
    cp_wait0();
    __syncthreads();

    const float* bias[3] = {bq, bk, bv};
    const int r0 = qb + 16 * w + (lane >> 2);
    const int c0 = 2 * (lane & 3);

#pragma unroll 1
    for (int m = 0; m < 3; m++) {
        float acc[16][4];
#pragma unroll
        for (int nt = 0; nt < 16; nt++) {
            float b0 = bias[m][nt * 8 + c0];
            float b1 = bias[m][nt * 8 + c0 + 1];
            acc[nt][0] = b0; acc[nt][1] = b1;
            acc[nt][2] = b0; acc[nt][3] = b1;
        }

#pragma unroll
        for (int kc = 0; kc < 16; kc++) {
            uint32_t al[4];
            ldmx4(al, sb + SM_X + aoff + kc * 32);
#pragma unroll
            for (int h = 0; h < 2; h++) {
                uint32_t Bh[4][4], Bl[4][4];
#pragma unroll
                for (int j = 0; j < 4; j++) {
                    uint32_t ro = (uint32_t)(h * 64 + j * 16) * XROW + kc * 32;
                    ldmx4(Bh[j], sb + SM_WH + boff + ro);
                    ldmx4(Bl[j], sb + SM_WL + boff + ro);
                }
                // three 8-MMA waves (accumulator reuse distance 8)
#pragma unroll
                for (int j = 0; j < 4; j++) {
                    mma16816h(acc[h * 8 + 2 * j],     xh[kc], &Bh[j][0]);
                    mma16816h(acc[h * 8 + 2 * j + 1], xh[kc], &Bh[j][2]);
                }
#pragma unroll
                for (int j = 0; j < 4; j++) {
                    mma16816h(acc[h * 8 + 2 * j],     al, &Bh[j][0]);
                    mma16816h(acc[h * 8 + 2 * j + 1], al, &Bh[j][2]);
                }
#pragma unroll
                for (int j = 0; j < 4; j++) {
                    mma16816h(acc[h * 8 + 2 * j],     xh[kc], &Bl[j][0]);
                    mma16816h(acc[h * 8 + 2 * j + 1], xh[kc], &Bl[j][2]);
                }
            }
        }

        // ---- epilogue ----
        if (m == 0) {
#pragma unroll
            for (int nt = 0; nt < 16; nt++) {
                uint32_t h0, l0, h1, l1;
                split2h(acc[nt][0], acc[nt][1], h0, l0);
                split2h(acc[nt][2], acc[nt][3], h1, l1);
                int col = nt * 8 + c0;
                *(uint32_t*)(g_Qhi + (size_t)r0 * PR_D + col)       = h0;
                *(uint32_t*)(g_Qlo + (size_t)r0 * PR_D + col)       = l0;
                *(uint32_t*)(g_Qhi + (size_t)(r0 + 8) * PR_D + col) = h1;
                *(uint32_t*)(g_Qlo + (size_t)(r0 + 8) * PR_D + col) = l1;
            }
        } else if (m == 1) {
#pragma unroll
            for (int nt = 0; nt < 16; nt++) {
                int col = nt * 8 + c0;
                *(uint32_t*)(g_Kh + (size_t)r0 * PR_D + col)
                    = pack_f16x2(acc[nt][0], acc[nt][1]);
                *(uint32_t*)(g_Kh + (size_t)(r0 + 8) * PR_D + col)
                    = pack_f16x2(acc[nt][2], acc[nt][3]);
            }
        } else {
            // V: stage fp16 tile into X region (272B rows), then write V^T
            __syncthreads();               // xl no longer needed by any warp
            const int rl = 16 * w + (lane >> 2);
#pragma unroll
            for (int nt = 0; nt < 16; nt++) {
                int col = nt * 8 + c0;
                *(uint32_t*)(sm + rl * 272 + col * 2)
                    = pack_f16x2(acc[nt][0], acc[nt][1]);
                *(uint32_t*)(sm + (rl + 8) * 272 + col * 2)
                    = pack_f16x2(acc[nt][2], acc[nt][3]);
            }
            __syncthreads();
            const int d  = t >> 1;
            const int hf = t & 1;
            uint32_t u[32];
#pragma unroll
            for (int j = 0; j < 32; j++) {
                uint32_t a = *(const uint16_t*)(sm + (hf * 64 + 2 * j) * 272 + d * 2);
                uint32_t b = *(const uint16_t*)(sm + (hf * 64 + 2 * j + 1) * 272 + d * 2);
                u[j] = (b << 16) | a;
            }
            uint4* dst = (uint4*)(g_VTh + (size_t)d * PR_N + qb + hf * 64);
#pragma unroll
            for (int q = 0; q < 8; q++)
                dst[q] = make_uint4(u[4 * q], u[4 * q + 1], u[4 * q + 2], u[4 * q + 3]);
        }

        // ---- prefetch next matrix WT ----
        if (m < 2) {
            __syncthreads();
#pragma unroll
            for (int i = 0; i < 16; i++) {
                int cid = t + i * 256;
                int r = cid >> 5, c = cid & 31;
                size_t o = (size_t)(m + 1) * PR_D * PR_INDIM + (size_t)r * PR_INDIM + c * 8;
                cp16(sb + SM_WH + r * XROW + c * 16, g_WTh + o);
                cp16(sb + SM_WL + r * XROW + c * 16, g_WTl + o);
            }
            cp_commit();
            cp_wait0();
            __syncthreads();
        }
    }
}

// ---------------------------------------------------------------------------
// Kernel 2: HMMA flash attention (unchanged from best: R9).
// ---------------------------------------------------------------------------
#define KROW   272
#define VROW   144
#define OFF_K  0
#define OFF_V  17408
#define ST_BYTES 35840
#define SM_BYTES (4 * ST_BYTES)    // 143360
#define NT (PR_N / 64)

__device__ __forceinline__ void load_stage(uint32_t dst, int kb)
{
    const int t = threadIdx.x;
#pragma unroll
    for (int i = 0; i < 4; i++) {
        int cid = t + i * 256;
        int r = cid >> 4, c = cid & 15;
        cp16(dst + OFF_K + r * KROW + c * 16, g_Kh + (size_t)(kb + r) * PR_D + c * 8);
    }
#pragma unroll
    for (int i = 0; i < 4; i++) {
        int cid = t + i * 256;
        int r = cid >> 3, c = cid & 7;
        cp16(dst + OFF_V + r * VROW + c * 16, g_VTh + (size_t)r * PR_N + kb + c * 8);
    }
}

__global__ void __launch_bounds__(256, 1) pr_attn_mma(float* __restrict__ out)
{
    extern __shared__ char sm[];
    const uint32_t sb = smem_u32(sm);

    const int t    = threadIdx.x;
    const int w    = t >> 5;
    const int lane = t & 31;
    const int qb   = blockIdx.x * 128;

    const uint32_t aRow = (uint32_t)(16 * w + (lane & 15));
    const uint32_t aCol = (uint32_t)(lane >> 4);
    const uint32_t bRow = (uint32_t)((lane & 7) + 8 * (lane >> 4));
    const uint32_t bCol = (uint32_t)((lane >> 3) & 1);
    const uint32_t bKoff = bRow * KROW + bCol * 16;
    const uint32_t bVoff = bRow * VROW + bCol * 16;

    // ---- stage Q (hi at sb, lo at sb+34816) and grab fragments ----
    {
#pragma unroll
        for (int i = 0; i < 8; i++) {
            int cid = t + i * 256;
            int r = cid >> 4, c = cid & 15;
            cp16(sb + r * KROW + c * 16,         g_Qhi + (size_t)(qb + r) * PR_D + c * 8);
            cp16(sb + 34816 + r * KROW + c * 16, g_Qlo + (size_t)(qb + r) * PR_D + c * 8);
        }
        cp_commit();
        cp_wait0();
        __syncthreads();
    }
    uint32_t qh[8][4], ql[8][4];
    {
        const uint32_t aQ = sb + aRow * KROW + aCol * 16;
#pragma unroll
        for (int kc = 0; kc < 8; kc++) {
            ldmx4(qh[kc], aQ + kc * 32);
            ldmx4(ql[kc], aQ + 34816 + kc * 32);
        }
    }
    __syncthreads();

    float o[16][4];
#pragma unroll
    for (int i = 0; i < 16; i++)
#pragma unroll
        for (int j = 0; j < 4; j++) o[i][j] = 0.0f;
    float lsum0 = 0.0f, lsum1 = 0.0f;
    float M0 = -1e30f, M1 = -1e30f;

    load_stage(sb + 0 * ST_BYTES, 0);
    cp_commit();
    load_stage(sb + 1 * ST_BYTES, 64);
    cp_commit();
    load_stage(sb + 2 * ST_BYTES, 128);
    cp_commit();

    int st_cur = 0, st_pre = 3;
#pragma unroll 1
    for (int tt = 0; tt < NT; tt++) {
        __syncthreads();
        if (tt + 3 < NT) load_stage(sb + st_pre * ST_BYTES, (tt + 3) * 64);
        cp_commit();
        cp_wait2();
        __syncthreads();

        const uint32_t p   = sb + st_cur * ST_BYTES;
        const uint32_t bKh = p + OFF_K + bKoff;
        const uint32_t bVh = p + OFF_V + bVoff;

        float s[8][4];
#pragma unroll
        for (int i = 0; i < 8; i++)
#pragma unroll
            for (int j = 0; j < 4; j++) s[i][j] = 0.0f;

#pragma unroll
        for (int kc = 0; kc < 8; kc++) {
            uint32_t bh[4][4];
#pragma unroll
            for (int jn = 0; jn < 4; jn++)
                ldmx4(bh[jn], bKh + jn * (16 * KROW) + kc * 32);
#pragma unroll
            for (int jn = 0; jn < 4; jn++) {
                mma16816h(s[2 * jn],     qh[kc], &bh[jn][0]);
                mma16816h(s[2 * jn + 1], qh[kc], &bh[jn][2]);
            }
#pragma unroll
            for (int jn = 0; jn < 4; jn++) {
                mma16816h(s[2 * jn],     ql[kc], &bh[jn][0]);
                mma16816h(s[2 * jn + 1], ql[kc], &bh[jn][2]);
            }
        }

        float m0 = s[0][0], m1 = s[0][2];
#pragma unroll
        for (int jt = 0; jt < 8; jt++) {
            m0 = fmaxf(m0, fmaxf(s[jt][0], s[jt][1]));
            m1 = fmaxf(m1, fmaxf(s[jt][2], s[jt][3]));
        }
        m0 = fmaxf(m0, __shfl_xor_sync(0xffffffffu, m0, 1));
        m0 = fmaxf(m0, __shfl_xor_sync(0xffffffffu, m0, 2));
        m1 = fmaxf(m1, __shfl_xor_sync(0xffffffffu, m1, 1));
        m1 = fmaxf(m1, __shfl_xor_sync(0xffffffffu, m1, 2));

        if (m0 > M0 || m1 > M1) {
            const float M0n = fmaxf(M0, m0), M1n = fmaxf(M1, m1);
            const float sc0 = ex2f((M0 - M0n) * LOG2E);
            const float sc1 = ex2f((M1 - M1n) * LOG2E);
            M0 = M0n; M1 = M1n;
            lsum0 *= sc0;
            lsum1 *= sc1;
#pragma unroll
            for (int dt = 0; dt < 16; dt++) {
                o[dt][0] *= sc0; o[dt][1] *= sc0;
                o[dt][2] *= sc1; o[dt][3] *= sc1;
            }
        }
        const float b0 = M0 * LOG2E, b1 = M1 * LOG2E;

        float ts0 = 0.0f, ts1 = 0.0f;
        uint32_t pp[16];
#pragma unroll
        for (int jt = 0; jt < 8; jt++) {
            float e0 = ex2f(fmaf(s[jt][0], LOG2E, -b0));
            float e1 = ex2f(fmaf(s[jt][1], LOG2E, -b0));
            float e2 = ex2f(fmaf(s[jt][2], LOG2E, -b1));
            float e3 = ex2f(fmaf(s[jt][3], LOG2E, -b1));
            ts0 += e0 + e1;
            ts1 += e2 + e3;
            pp[2 * jt]     = pack_f16x2(e0, e1);
            pp[2 * jt + 1] = pack_f16x2(e2, e3);
        }
        lsum0 += ts0;
        lsum1 += ts1;

        uint32_t v[2][4];
        ldmx4(v[0], bVh);
#pragma unroll
        for (int idx = 0; idx < 32; idx++) {
            const int cur = idx & 1, nxt = cur ^ 1;
            if (idx < 31) {
                const int kc2 = (idx + 1) >> 3, dn2 = (idx + 1) & 7;
                ldmx4(v[nxt], bVh + dn2 * (16 * VROW) + kc2 * 32);
            }
            const int kc = idx >> 3, dn = idx & 7;
            mma16816h(o[2 * dn],     &pp[4 * kc], &v[cur][0]);
            mma16816h(o[2 * dn + 1], &pp[4 * kc], &v[cur][2]);
        }

        st_cur = (st_cur + 1) & 3;
        st_pre = (st_pre + 1) & 3;
    }

    lsum0 += __shfl_xor_sync(0xffffffffu, lsum0, 1);
    lsum0 += __shfl_xor_sync(0xffffffffu, lsum0, 2);
    lsum1 += __shfl_xor_sync(0xffffffffu, lsum1, 1);
    lsum1 += __shfl_xor_sync(0xffffffffu, lsum1, 2);
    const float inv0 = 1.0f / lsum0;
    const float inv1 = 1.0f / lsum1;

    const int r0 = qb + 16 * w + (lane >> 2);
    const int cb = 2 * (lane & 3);
#pragma unroll
    for (int dt = 0; dt < 16; dt++) {
        float2 v0 = make_float2(o[dt][0] * inv0, o[dt][1] * inv0);
        float2 v1 = make_float2(o[dt][2] * inv1, o[dt][3] * inv1);
        *(float2*)(out + (size_t)r0 * PR_D + 8 * dt + cb)       = v0;
        *(float2*)(out + (size_t)(r0 + 8) * PR_D + 8 * dt + cb) = v1;
    }
}

// ---------------------------------------------------------------------------
extern "C" void kernel_launch(void* const* d_in, const int* in_sizes, int n_in,
                              void* d_out, int out_size)
{
    const float* x  = (const float*)d_in[0];
    const float* Wq = (const float*)d_in[1];
    const float* bq = (const float*)d_in[2];
    const float* Wk = (const float*)d_in[3];
    const float* bk = (const float*)d_in[4];
    const float* Wv = (const float*)d_in[5];
    const float* bv = (const float*)d_in[6];
    float* out = (float*)d_out;

    pr_convert<<<2096, 256>>>(x, Wq, Wk, Wv);

    cudaFuncSetAttribute(pr_proj_mma,
                         cudaFuncAttributeMaxDynamicSharedMemorySize, PROJ_SM);
    pr_proj_mma<<<PR_N / 128, 256, PROJ_SM>>>(bq, bk, bv);

    cudaFuncSetAttribute(pr_attn_mma,
                         cudaFuncAttributeMaxDynamicSharedMemorySize, SM_BYTES);
    pr_attn_mma<<<PR_N / 128, 256, SM_BYTES>>>(out);
}

// round 13
// speedup vs baseline: 1.5434x; 1.0644x over previous
#include <cuda_runtime.h>
#include <cuda_fp16.h>
#include <cstdint>
#include <cstddef>

#define PR_N      16384
#define PR_INDIM  256
#define PR_D      128
#define LOG2E     1.4426950408889634f
#define KSPLIT    8
#define KEYS_PER  (PR_N / KSPLIT)      // 2048
#define NTS       (KEYS_PER / 64)      // 32 subtiles per CTA

// ---------------- scratch ---------------------------------------------------
__device__ __align__(16) __half g_Qhi[PR_N * PR_D];
__device__ __align__(16) __half g_Qlo[PR_N * PR_D];
__device__ __align__(16) __half g_Kh [PR_N * PR_D];
__device__ __align__(16) __half g_VTh[PR_D * PR_N];        // V^T [d][n]
__device__ __align__(16) __half g_xh [PR_N * PR_INDIM];
__device__ __align__(16) __half g_xl [PR_N * PR_INDIM];
__device__ __align__(16) __half g_WTh[3 * PR_D * PR_INDIM];
__device__ __align__(16) __half g_WTl[3 * PR_D * PR_INDIM];
// split-K partials
__device__ __align__(16) float  g_pO[KSPLIT * PR_N * PR_D];  // 64 MB
__device__ __align__(16) float  g_pM[KSPLIT * PR_N];
__device__ __align__(16) float  g_pL[KSPLIT * PR_N];

// ---------------- helpers ---------------------------------------------------
__device__ __forceinline__ uint32_t smem_u32(const void* p) {
    uint32_t a;
    asm("{ .reg .u64 t; cvta.to.shared.u64 t, %1; cvt.u32.u64 %0, t; }"
        : "=r"(a) : "l"(p));
    return a;
}
__device__ __forceinline__ float ex2f(float x) {
    float r;
    asm("ex2.approx.ftz.f32 %0, %1;" : "=f"(r) : "f"(x));
    return r;
}
__device__ __forceinline__ uint32_t pack_f16x2(float a, float b) {
    uint32_t r;
    asm("cvt.rn.f16x2.f32 %0, %1, %2;" : "=r"(r) : "f"(b), "f"(a));
    return r;
}
__device__ __forceinline__ void split2h(float f0, float f1, uint32_t& hi, uint32_t& lo) {
    __half a0 = __float2half_rn(f0), a1 = __float2half_rn(f1);
    hi = ((uint32_t)__half_as_ushort(a1) << 16) | __half_as_ushort(a0);
    lo = pack_f16x2(f0 - __half2float(a0), f1 - __half2float(a1));
}
__device__ __forceinline__ void ldmx4(uint32_t* r, uint32_t addr) {
    asm volatile("ldmatrix.sync.aligned.m8n8.x4.shared.b16 {%0,%1,%2,%3}, [%4];"
                 : "=r"(r[0]), "=r"(r[1]), "=r"(r[2]), "=r"(r[3]) : "r"(addr));
}
__device__ __forceinline__ void mma16816h(float* c, const uint32_t* a,
                                          const uint32_t* b) {
    asm volatile(
        "mma.sync.aligned.m16n8k16.row.col.f32.f16.f16.f32 "
        "{%0,%1,%2,%3}, {%4,%5,%6,%7}, {%8,%9}, {%0,%1,%2,%3};"
        : "+f"(c[0]), "+f"(c[1]), "+f"(c[2]), "+f"(c[3])
        : "r"(a[0]), "r"(a[1]), "r"(a[2]), "r"(a[3]), "r"(b[0]), "r"(b[1]));
}
__device__ __forceinline__ void cp16(uint32_t dst, const void* src) {
    asm volatile("cp.async.cg.shared.global [%0], [%1], 16;"
                 :: "r"(dst), "l"(src) : "memory");
}
__device__ __forceinline__ void cp_commit() {
    asm volatile("cp.async.commit_group;" ::: "memory");
}
__device__ __forceinline__ void cp_wait2() {
    asm volatile("cp.async.wait_group 2;" ::: "memory");
}
__device__ __forceinline__ void cp_wait0() {
    asm volatile("cp.async.wait_group 0;" ::: "memory");
}

// ---------------------------------------------------------------------------
// Kernel 0: convert x -> fp16 hi/lo; W -> W^T fp16 hi/lo.
// ---------------------------------------------------------------------------
__global__ void __launch_bounds__(256) pr_convert(
    const float* __restrict__ x,
    const float* __restrict__ Wq, const float* __restrict__ Wk,
    const float* __restrict__ Wv)
{
    const int bid = blockIdx.x, t = threadIdx.x;
    if (bid < 2048) {
        size_t e0 = ((size_t)bid * 256 + t) * 8;
        float4 f0 = *(const float4*)(x + e0);
        float4 f1 = *(const float4*)(x + e0 + 4);
        uint32_t h[4], l[4];
        split2h(f0.x, f0.y, h[0], l[0]);
        split2h(f0.z, f0.w, h[1], l[1]);
        split2h(f1.x, f1.y, h[2], l[2]);
        split2h(f1.z, f1.w, h[3], l[3]);
        *(uint4*)(g_xh + e0) = make_uint4(h[0], h[1], h[2], h[3]);
        *(uint4*)(g_xl + e0) = make_uint4(l[0], l[1], l[2], l[3]);
    } else {
        int idx = (bid - 2048) * 256 + t;
        int m   = idx >> 12;
        int rem = idx & 4095;
        int d   = rem >> 5;
        int k0  = (rem & 31) * 8;
        const float* W = (m == 0) ? Wq : ((m == 1) ? Wk : Wv);
        uint32_t h[4], l[4];
#pragma unroll
        for (int i = 0; i < 4; i++) {
            float a = W[(size_t)(k0 + 2 * i) * PR_D + d];
            float b = W[(size_t)(k0 + 2 * i + 1) * PR_D + d];
            split2h(a, b, h[i], l[i]);
        }
        size_t o = ((size_t)m * PR_D + d) * PR_INDIM + k0;
        *(uint4*)(g_WTh + o) = make_uint4(h[0], h[1], h[2], h[3]);
        *(uint4*)(g_WTl + o) = make_uint4(l[0], l[1], l[2], l[3]);
    }
}

// ---------------------------------------------------------------------------
// Kernel 1: HMMA projection, 3-pass split fp16 (unchanged from R11).
// ---------------------------------------------------------------------------
#define XROW    528
#define SM_X    0
#define SM_WH   67584
#define SM_WL   135168
#define PROJ_SM 202752

__global__ void __launch_bounds__(256, 1) pr_proj_mma(
    const float* __restrict__ bq, const float* __restrict__ bk,
    const float* __restrict__ bv)
{
    extern __shared__ char sm[];
    const uint32_t sb = smem_u32(sm);

    const int t    = threadIdx.x;
    const int w    = t >> 5;
    const int lane = t & 31;
    const int qb   = blockIdx.x * 128;

    const uint32_t aoff = (uint32_t)(16 * w + (lane & 15)) * XROW
                        + (uint32_t)(lane >> 4) * 16;
    const uint32_t boff = (uint32_t)((lane & 7) + 8 * (lane >> 4)) * XROW
                        + (uint32_t)((lane >> 3) & 1) * 16;

#pragma unroll
    for (int i = 0; i < 16; i++) {
        int cid = t + i * 256;
        int r = cid >> 5, c = cid & 31;
        cp16(sb + SM_X + r * XROW + c * 16, g_xh + (size_t)(qb + r) * PR_INDIM + c * 8);
    }
    cp_commit();
    cp_wait0();
    __syncthreads();

    uint32_t xh[16][4];
#pragma unroll
    for (int kc = 0; kc < 16; kc++)
        ldmx4(xh[kc], sb + SM_X + aoff + kc * 32);
    __syncthreads();

#pragma unroll
    for (int i = 0; i < 16; i++) {
        int cid = t + i * 256;
        int r = cid >> 5, c = cid & 31;
        cp16(sb + SM_X + r * XROW + c * 16, g_xl + (size_t)(qb + r) * PR_INDIM + c * 8);
        cp16(sb + SM_WH + r * XROW + c * 16, g_WTh + (size_t)r * PR_INDIM + c * 8);
        cp16(sb + SM_WL + r * XROW + c * 16, g_WTl + (size_t)r * PR_INDIM + c * 8);
    }
    cp_commit();
    cp_wait0();
    __syncthreads();

    const float* bias[3] = {bq, bk, bv};
    const int r0 = qb + 16 * w + (lane >> 2);
    const int c0 = 2 * (lane & 3);

#pragma unroll 1
    for (int m = 0; m < 3; m++) {
        float acc[16][4];
#pragma unroll
        for (int nt = 0; nt < 16; nt++) {
            float b0 = bias[m][nt * 8 + c0];
            float b1 = bias[m][nt * 8 + c0 + 1];
            acc[nt][0] = b0; acc[nt][1] = b1;
            acc[nt][2] = b0; acc[nt][3] = b1;
        }

#pragma unroll
        for (int kc = 0; kc < 16; kc++) {
            uint32_t al[4];
            ldmx4(al, sb + SM_X + aoff + kc * 32);
#pragma unroll
            for (int h = 0; h < 2; h++) {
                uint32_t Bh[4][4], Bl[4][4];
#pragma unroll
                for (int j = 0; j < 4; j++) {
                    uint32_t ro = (uint32_t)(h * 64 + j * 16) * XROW + kc * 32;
                    ldmx4(Bh[j], sb + SM_WH + boff + ro);
                    ldmx4(Bl[j], sb + SM_WL + boff + ro);
                }
#pragma unroll
                for (int j = 0; j < 4; j++) {
                    mma16816h(acc[h * 8 + 2 * j],     xh[kc], &Bh[j][0]);
                    mma16816h(acc[h * 8 + 2 * j + 1], xh[kc], &Bh[j][2]);
                }
#pragma unroll
                for (int j = 0; j < 4; j++) {
                    mma16816h(acc[h * 8 + 2 * j],     al, &Bh[j][0]);
                    mma16816h(acc[h * 8 + 2 * j + 1], al, &Bh[j][2]);
                }
#pragma unroll
                for (int j = 0; j < 4; j++) {
                    mma16816h(acc[h * 8 + 2 * j],     xh[kc], &Bl[j][0]);
                    mma16816h(acc[h * 8 + 2 * j + 1], xh[kc], &Bl[j][2]);
                }
            }
        }

        if (m == 0) {
#pragma unroll
            for (int nt = 0; nt < 16; nt++) {
                uint32_t h0, l0, h1, l1;
                split2h(acc[nt][0], acc[nt][1], h0, l0);
                split2h(acc[nt][2], acc[nt][3], h1, l1);
                int col = nt * 8 + c0;
                *(uint32_t*)(g_Qhi + (size_t)r0 * PR_D + col)       = h0;
                *(uint32_t*)(g_Qlo + (size_t)r0 * PR_D + col)       = l0;
                *(uint32_t*)(g_Qhi + (size_t)(r0 + 8) * PR_D + col) = h1;
                *(uint32_t*)(g_Qlo + (size_t)(r0 + 8) * PR_D + col) = l1;
            }
        } else if (m == 1) {
#pragma unroll
            for (int nt = 0; nt < 16; nt++) {
                int col = nt * 8 + c0;
                *(uint32_t*)(g_Kh + (size_t)r0 * PR_D + col)
                    = pack_f16x2(acc[nt][0], acc[nt][1]);
                *(uint32_t*)(g_Kh + (size_t)(r0 + 8) * PR_D + col)
                    = pack_f16x2(acc[nt][2], acc[nt][3]);
            }
        } else {
            __syncthreads();
            const int rl = 16 * w + (lane >> 2);
#pragma unroll
            for (int nt = 0; nt < 16; nt++) {
                int col = nt * 8 + c0;
                *(uint32_t*)(sm + rl * 272 + col * 2)
                    = pack_f16x2(acc[nt][0], acc[nt][1]);
                *(uint32_t*)(sm + (rl + 8) * 272 + col * 2)
                    = pack_f16x2(acc[nt][2], acc[nt][3]);
            }
            __syncthreads();
            const int d  = t >> 1;
            const int hf = t & 1;
            uint32_t u[32];
#pragma unroll
            for (int j = 0; j < 32; j++) {
                uint32_t a = *(const uint16_t*)(sm + (hf * 64 + 2 * j) * 272 + d * 2);
                uint32_t b = *(const uint16_t*)(sm + (hf * 64 + 2 * j + 1) * 272 + d * 2);
                u[j] = (b << 16) | a;
            }
            uint4* dst = (uint4*)(g_VTh + (size_t)d * PR_N + qb + hf * 64);
#pragma unroll
            for (int q = 0; q < 8; q++)
                dst[q] = make_uint4(u[4 * q], u[4 * q + 1], u[4 * q + 2], u[4 * q + 3]);
        }

        if (m < 2) {
            __syncthreads();
#pragma unroll
            for (int i = 0; i < 16; i++) {
                int cid = t + i * 256;
                int r = cid >> 5, c = cid & 31;
                size_t o = (size_t)(m + 1) * PR_D * PR_INDIM + (size_t)r * PR_INDIM + c * 8;
                cp16(sb + SM_WH + r * XROW + c * 16, g_WTh + o);
                cp16(sb + SM_WL + r * XROW + c * 16, g_WTl + o);
            }
            cp_commit();
            cp_wait0();
            __syncthreads();
        }
    }
}

// ---------------------------------------------------------------------------
// Kernel 2: HMMA flash attention, split-K x8.  grid = 1024 (128 qt x 8 ks).
// Inner loop identical to the proven R9 kernel; epilogue writes un-normalized
// partials (O, M, lsum) for the merge kernel.
// ---------------------------------------------------------------------------
#define KROW   272
#define VROW   144
#define OFF_K  0
#define OFF_V  17408
#define ST_BYTES 35840
#define SM_BYTES (4 * ST_BYTES)    // 143360

__device__ __forceinline__ void load_stage(uint32_t dst, int kb)
{
    const int t = threadIdx.x;
#pragma unroll
    for (int i = 0; i < 4; i++) {
        int cid = t + i * 256;
        int r = cid >> 4, c = cid & 15;
        cp16(dst + OFF_K + r * KROW + c * 16, g_Kh + (size_t)(kb + r) * PR_D + c * 8);
    }
#pragma unroll
    for (int i = 0; i < 4; i++) {
        int cid = t + i * 256;
        int r = cid >> 3, c = cid & 7;
        cp16(dst + OFF_V + r * VROW + c * 16, g_VTh + (size_t)r * PR_N + kb + c * 8);
    }
}

__global__ void __launch_bounds__(256, 1) pr_attn_mma()
{
    extern __shared__ char sm[];
    const uint32_t sb = smem_u32(sm);

    const int t     = threadIdx.x;
    const int w     = t >> 5;
    const int lane  = t & 31;
    const int qb    = (blockIdx.x >> 3) * 128;
    const int ks    = blockIdx.x & 7;
    const int kbase = ks * KEYS_PER;

    const uint32_t aRow = (uint32_t)(16 * w + (lane & 15));
    const uint32_t aCol = (uint32_t)(lane >> 4);
    const uint32_t bRow = (uint32_t)((lane & 7) + 8 * (lane >> 4));
    const uint32_t bCol = (uint32_t)((lane >> 3) & 1);
    const uint32_t bKoff = bRow * KROW + bCol * 16;
    const uint32_t bVoff = bRow * VROW + bCol * 16;

    // ---- stage Q (hi at sb, lo at sb+34816) and grab fragments ----
    {
#pragma unroll
        for (int i = 0; i < 8; i++) {
            int cid = t + i * 256;
            int r = cid >> 4, c = cid & 15;
            cp16(sb + r * KROW + c * 16,         g_Qhi + (size_t)(qb + r) * PR_D + c * 8);
            cp16(sb + 34816 + r * KROW + c * 16, g_Qlo + (size_t)(qb + r) * PR_D + c * 8);
        }
        cp_commit();
        cp_wait0();
        __syncthreads();
    }
    uint32_t qh[8][4], ql[8][4];
    {
        const uint32_t aQ = sb + aRow * KROW + aCol * 16;
#pragma unroll
        for (int kc = 0; kc < 8; kc++) {
            ldmx4(qh[kc], aQ + kc * 32);
            ldmx4(ql[kc], aQ + 34816 + kc * 32);
        }
    }
    __syncthreads();

    float o[16][4];
#pragma unroll
    for (int i = 0; i < 16; i++)
#pragma unroll
        for (int j = 0; j < 4; j++) o[i][j] = 0.0f;
    float lsum0 = 0.0f, lsum1 = 0.0f;
    float M0 = -1e30f, M1 = -1e30f;

    load_stage(sb + 0 * ST_BYTES, kbase);
    cp_commit();
    load_stage(sb + 1 * ST_BYTES, kbase + 64);
    cp_commit();
    load_stage(sb + 2 * ST_BYTES, kbase + 128);
    cp_commit();

    int st_cur = 0, st_pre = 3;
#pragma unroll 1
    for (int tt = 0; tt < NTS; tt++) {
        __syncthreads();
        if (tt + 3 < NTS) load_stage(sb + st_pre * ST_BYTES, kbase + (tt + 3) * 64);
        cp_commit();
        cp_wait2();
        __syncthreads();

        const uint32_t p   = sb + st_cur * ST_BYTES;
        const uint32_t bKh = p + OFF_K + bKoff;
        const uint32_t bVh = p + OFF_V + bVoff;

        float s[8][4];
#pragma unroll
        for (int i = 0; i < 8; i++)
#pragma unroll
            for (int j = 0; j < 4; j++) s[i][j] = 0.0f;

#pragma unroll
        for (int kc = 0; kc < 8; kc++) {
            uint32_t bh[4][4];
#pragma unroll
            for (int jn = 0; jn < 4; jn++)
                ldmx4(bh[jn], bKh + jn * (16 * KROW) + kc * 32);
#pragma unroll
            for (int jn = 0; jn < 4; jn++) {
                mma16816h(s[2 * jn],     qh[kc], &bh[jn][0]);
                mma16816h(s[2 * jn + 1], qh[kc], &bh[jn][2]);
            }
#pragma unroll
            for (int jn = 0; jn < 4; jn++) {
                mma16816h(s[2 * jn],     ql[kc], &bh[jn][0]);
                mma16816h(s[2 * jn + 1], ql[kc], &bh[jn][2]);
            }
        }

        float m0 = s[0][0], m1 = s[0][2];
#pragma unroll
        for (int jt = 0; jt < 8; jt++) {
            m0 = fmaxf(m0, fmaxf(s[jt][0], s[jt][1]));
            m1 = fmaxf(m1, fmaxf(s[jt][2], s[jt][3]));
        }
        m0 = fmaxf(m0, __shfl_xor_sync(0xffffffffu, m0, 1));
        m0 = fmaxf(m0, __shfl_xor_sync(0xffffffffu, m0, 2));
        m1 = fmaxf(m1, __shfl_xor_sync(0xffffffffu, m1, 1));
        m1 = fmaxf(m1, __shfl_xor_sync(0xffffffffu, m1, 2));

        if (m0 > M0 || m1 > M1) {
            const float M0n = fmaxf(M0, m0), M1n = fmaxf(M1, m1);
            const float sc0 = ex2f((M0 - M0n) * LOG2E);
            const float sc1 = ex2f((M1 - M1n) * LOG2E);
            M0 = M0n; M1 = M1n;
            lsum0 *= sc0;
            lsum1 *= sc1;
#pragma unroll
            for (int dt = 0; dt < 16; dt++) {
                o[dt][0] *= sc0; o[dt][1] *= sc0;
                o[dt][2] *= sc1; o[dt][3] *= sc1;
            }
        }
        const float b0 = M0 * LOG2E, b1 = M1 * LOG2E;

        float ts0 = 0.0f, ts1 = 0.0f;
        uint32_t pp[16];
#pragma unroll
        for (int jt = 0; jt < 8; jt++) {
            float e0 = ex2f(fmaf(s[jt][0], LOG2E, -b0));
            float e1 = ex2f(fmaf(s[jt][1], LOG2E, -b0));
            float e2 = ex2f(fmaf(s[jt][2], LOG2E, -b1));
            float e3 = ex2f(fmaf(s[jt][3], LOG2E, -b1));
            ts0 += e0 + e1;
            ts1 += e2 + e3;
            pp[2 * jt]     = pack_f16x2(e0, e1);
            pp[2 * jt + 1] = pack_f16x2(e2, e3);
        }
        lsum0 += ts0;
        lsum1 += ts1;

        uint32_t v[2][4];
        ldmx4(v[0], bVh);
#pragma unroll
        for (int idx = 0; idx < 32; idx++) {
            const int cur = idx & 1, nxt = cur ^ 1;
            if (idx < 31) {
                const int kc2 = (idx + 1) >> 3, dn2 = (idx + 1) & 7;
                ldmx4(v[nxt], bVh + dn2 * (16 * VROW) + kc2 * 32);
            }
            const int kc = idx >> 3, dn = idx & 7;
            mma16816h(o[2 * dn],     &pp[4 * kc], &v[cur][0]);
            mma16816h(o[2 * dn + 1], &pp[4 * kc], &v[cur][2]);
        }

        st_cur = (st_cur + 1) & 3;
        st_pre = (st_pre + 1) & 3;
    }

    // ---- epilogue: reduce lsum over the lane quad, write partials ----
    lsum0 += __shfl_xor_sync(0xffffffffu, lsum0, 1);
    lsum0 += __shfl_xor_sync(0xffffffffu, lsum0, 2);
    lsum1 += __shfl_xor_sync(0xffffffffu, lsum1, 1);
    lsum1 += __shfl_xor_sync(0xffffffffu, lsum1, 2);

    const int r0 = qb + 16 * w + (lane >> 2);
    const int cb = 2 * (lane & 3);
    float* pO = g_pO + ((size_t)ks * PR_N) * PR_D;
#pragma unroll
    for (int dt = 0; dt < 16; dt++) {
        *(float2*)(pO + (size_t)r0 * PR_D + 8 * dt + cb)
            = make_float2(o[dt][0], o[dt][1]);
        *(float2*)(pO + (size_t)(r0 + 8) * PR_D + 8 * dt + cb)
            = make_float2(o[dt][2], o[dt][3]);
    }
    if ((lane & 3) == 0) {
        g_pM[ks * PR_N + r0]     = M0;
        g_pL[ks * PR_N + r0]     = lsum0;
        g_pM[ks * PR_N + r0 + 8] = M1;
        g_pL[ks * PR_N + r0 + 8] = lsum1;
    }
}

// ---------------------------------------------------------------------------
// Kernel 3: merge the 8 split-K partial softmaxes.  grid=2048 x 256.
// thread -> (row, 4-col chunk): 16384 rows x 32 chunks.
// ---------------------------------------------------------------------------
__global__ void __launch_bounds__(256) pr_merge(float* __restrict__ out)
{
    const int g   = blockIdx.x * 256 + threadIdx.x;   // 524288
    const int row = g >> 5;
    const int c4  = (g & 31) * 4;

    float M = -1e30f;
#pragma unroll
    for (int i = 0; i < KSPLIT; i++)
        M = fmaxf(M, g_pM[i * PR_N + row]);

    float wsum = 0.0f;
    float4 acc = make_float4(0.0f, 0.0f, 0.0f, 0.0f);
#pragma unroll
    for (int i = 0; i < KSPLIT; i++) {
        float sc = ex2f((g_pM[i * PR_N + row] - M) * LOG2E);
        wsum = fmaf(g_pL[i * PR_N + row], sc, wsum);
        float4 v = *(const float4*)(g_pO + ((size_t)i * PR_N + row) * PR_D + c4);
        acc.x = fmaf(v.x, sc, acc.x);
        acc.y = fmaf(v.y, sc, acc.y);
        acc.z = fmaf(v.z, sc, acc.z);
        acc.w = fmaf(v.w, sc, acc.w);
    }
    const float inv = 1.0f / wsum;
    acc.x *= inv; acc.y *= inv; acc.z *= inv; acc.w *= inv;
    *(float4*)(out + (size_t)row * PR_D + c4) = acc;
}

// ---------------------------------------------------------------------------
extern "C" void kernel_launch(void* const* d_in, const int* in_sizes, int n_in,
                              void* d_out, int out_size)
{
    const float* x  = (const float*)d_in[0];
    const float* Wq = (const float*)d_in[1];
    const float* bq = (const float*)d_in[2];
    const float* Wk = (const float*)d_in[3];
    const float* bk = (const float*)d_in[4];
    const float* Wv = (const float*)d_in[5];
    const float* bv = (const float*)d_in[6];
    float* out = (float*)d_out;

    pr_convert<<<2096, 256>>>(x, Wq, Wk, Wv);

    cudaFuncSetAttribute(pr_proj_mma,
                         cudaFuncAttributeMaxDynamicSharedMemorySize, PROJ_SM);
    pr_proj_mma<<<PR_N / 128, 256, PROJ_SM>>>(bq, bk, bv);

    cudaFuncSetAttribute(pr_attn_mma,
                         cudaFuncAttributeMaxDynamicSharedMemorySize, SM_BYTES);
    pr_attn_mma<<<(PR_N / 128) * KSPLIT, 256, SM_BYTES>>>();

    pr_merge<<<2048, 256>>>(out);
}

// round 14
// speedup vs baseline: 1.8527x; 1.2004x over previous
#include <cuda_runtime.h>
#include <cuda_fp16.h>
#include <cstdint>
#include <cstddef>

#define PR_N      16384
#define PR_INDIM  256
#define PR_D      128
#define LOG2E     1.4426950408889634f
#define KSPLIT    8
#define KEYS_PER  (PR_N / KSPLIT)      // 2048
#define NTS       (KEYS_PER / 64)      // 32 subtiles per CTA

// ---------------- scratch ---------------------------------------------------
__device__ __align__(16) __half g_Qh [PR_N * PR_D];
__device__ __align__(16) __half g_Kh [PR_N * PR_D];
__device__ __align__(16) __half g_VTh[PR_D * PR_N];        // V^T [d][n]
__device__ __align__(16) __half g_xh [PR_N * PR_INDIM];
__device__ __align__(16) __half g_xl [PR_N * PR_INDIM];
__device__ __align__(16) __half g_WTh[3 * PR_D * PR_INDIM];
__device__ __align__(16) __half g_WTl[3 * PR_D * PR_INDIM];
// split-K partials (O normalized per split, stored fp16)
__device__ __align__(16) __half g_pO[KSPLIT * PR_N * PR_D];  // 32 MB
__device__ __align__(16) float  g_pM[KSPLIT * PR_N];
__device__ __align__(16) float  g_pL[KSPLIT * PR_N];

// ---------------- helpers ---------------------------------------------------
__device__ __forceinline__ uint32_t smem_u32(const void* p) {
    uint32_t a;
    asm("{ .reg .u64 t; cvta.to.shared.u64 t, %1; cvt.u32.u64 %0, t; }"
        : "=r"(a) : "l"(p));
    return a;
}
__device__ __forceinline__ float ex2f(float x) {
    float r;
    asm("ex2.approx.ftz.f32 %0, %1;" : "=f"(r) : "f"(x));
    return r;
}
__device__ __forceinline__ uint32_t pack_f16x2(float a, float b) {
    uint32_t r;
    asm("cvt.rn.f16x2.f32 %0, %1, %2;" : "=r"(r) : "f"(b), "f"(a));
    return r;
}
__device__ __forceinline__ void split2h(float f0, float f1, uint32_t& hi, uint32_t& lo) {
    __half a0 = __float2half_rn(f0), a1 = __float2half_rn(f1);
    hi = ((uint32_t)__half_as_ushort(a1) << 16) | __half_as_ushort(a0);
    lo = pack_f16x2(f0 - __half2float(a0), f1 - __half2float(a1));
}
__device__ __forceinline__ void ldmx4(uint32_t* r, uint32_t addr) {
    asm volatile("ldmatrix.sync.aligned.m8n8.x4.shared.b16 {%0,%1,%2,%3}, [%4];"
                 : "=r"(r[0]), "=r"(r[1]), "=r"(r[2]), "=r"(r[3]) : "r"(addr));
}
__device__ __forceinline__ void mma16816h(float* c, const uint32_t* a,
                                          const uint32_t* b) {
    asm volatile(
        "mma.sync.aligned.m16n8k16.row.col.f32.f16.f16.f32 "
        "{%0,%1,%2,%3}, {%4,%5,%6,%7}, {%8,%9}, {%0,%1,%2,%3};"
        : "+f"(c[0]), "+f"(c[1]), "+f"(c[2]), "+f"(c[3])
        : "r"(a[0]), "r"(a[1]), "r"(a[2]), "r"(a[3]), "r"(b[0]), "r"(b[1]));
}
__device__ __forceinline__ void cp16(uint32_t dst, const void* src) {
    asm volatile("cp.async.cg.shared.global [%0], [%1], 16;"
                 :: "r"(dst), "l"(src) : "memory");
}
__device__ __forceinline__ void cp_commit() {
    asm volatile("cp.async.commit_group;" ::: "memory");
}
__device__ __forceinline__ void cp_wait2() {
    asm volatile("cp.async.wait_group 2;" ::: "memory");
}
__device__ __forceinline__ void cp_wait0() {
    asm volatile("cp.async.wait_group 0;" ::: "memory");
}

// ---------------------------------------------------------------------------
// Kernel 0: convert x -> fp16 hi/lo; W -> W^T fp16 hi/lo.
// ---------------------------------------------------------------------------
__global__ void __launch_bounds__(256) pr_convert(
    const float* __restrict__ x,
    const float* __restrict__ Wq, const float* __restrict__ Wk,
    const float* __restrict__ Wv)
{
    const int bid = blockIdx.x, t = threadIdx.x;
    if (bid < 2048) {
        size_t e0 = ((size_t)bid * 256 + t) * 8;
        float4 f0 = *(const float4*)(x + e0);
        float4 f1 = *(const float4*)(x + e0 + 4);
        uint32_t h[4], l[4];
        split2h(f0.x, f0.y, h[0], l[0]);
        split2h(f0.z, f0.w, h[1], l[1]);
        split2h(f1.x, f1.y, h[2], l[2]);
        split2h(f1.z, f1.w, h[3], l[3]);
        *(uint4*)(g_xh + e0) = make_uint4(h[0], h[1], h[2], h[3]);
        *(uint4*)(g_xl + e0) = make_uint4(l[0], l[1], l[2], l[3]);
    } else {
        int idx = (bid - 2048) * 256 + t;
        int m   = idx >> 12;
        int rem = idx & 4095;
        int d   = rem >> 5;
        int k0  = (rem & 31) * 8;
        const float* W = (m == 0) ? Wq : ((m == 1) ? Wk : Wv);
        uint32_t h[4], l[4];
#pragma unroll
        for (int i = 0; i < 4; i++) {
            float a = W[(size_t)(k0 + 2 * i) * PR_D + d];
            float b = W[(size_t)(k0 + 2 * i + 1) * PR_D + d];
            split2h(a, b, h[i], l[i]);
        }
        size_t o = ((size_t)m * PR_D + d) * PR_INDIM + k0;
        *(uint4*)(g_WTh + o) = make_uint4(h[0], h[1], h[2], h[3]);
        *(uint4*)(g_WTl + o) = make_uint4(l[0], l[1], l[2], l[3]);
    }
}

// ---------------------------------------------------------------------------
// Kernel 1: HMMA projection, 3-pass split fp16 (Q now stored single fp16).
// ---------------------------------------------------------------------------
#define XROW    528
#define SM_X    0
#define SM_WH   67584
#define SM_WL   135168
#define PROJ_SM 202752

__global__ void __launch_bounds__(256, 1) pr_proj_mma(
    const float* __restrict__ bq, const float* __restrict__ bk,
    const float* __restrict__ bv)
{
    extern __shared__ char sm[];
    const uint32_t sb = smem_u32(sm);

    const int t    = threadIdx.x;
    const int w    = t >> 5;
    const int lane = t & 31;
    const int qb   = blockIdx.x * 128;

    const uint32_t aoff = (uint32_t)(16 * w + (lane & 15)) * XROW
                        + (uint32_t)(lane >> 4) * 16;
    const uint32_t boff = (uint32_t)((lane & 7) + 8 * (lane >> 4)) * XROW
                        + (uint32_t)((lane >> 3) & 1) * 16;

#pragma unroll
    for (int i = 0; i < 16; i++) {
        int cid = t + i * 256;
        int r = cid >> 5, c = cid & 31;
        cp16(sb + SM_X + r * XROW + c * 16, g_xh + (size_t)(qb + r) * PR_INDIM + c * 8);
    }
    cp_commit();
    cp_wait0();
    __syncthreads();

    uint32_t xh[16][4];
#pragma unroll
    for (int kc = 0; kc < 16; kc++)
        ldmx4(xh[kc], sb + SM_X + aoff + kc * 32);
    __syncthreads();

#pragma unroll
    for (int i = 0; i < 16; i++) {
        int cid = t + i * 256;
        int r = cid >> 5, c = cid & 31;
        cp16(sb + SM_X + r * XROW + c * 16, g_xl + (size_t)(qb + r) * PR_INDIM + c * 8);
        cp16(sb + SM_WH + r * XROW + c * 16, g_WTh + (size_t)r * PR_INDIM + c * 8);
        cp16(sb + SM_WL + r * XROW + c * 16, g_WTl + (size_t)r * PR_INDIM + c * 8);
    }
    cp_commit();
    cp_wait0();
    __syncthreads();

    const float* bias[3] = {bq, bk, bv};
    const int r0 = qb + 16 * w + (lane >> 2);
    const int c0 = 2 * (lane & 3);

#pragma unroll 1
    for (int m = 0; m < 3; m++) {
        float acc[16][4];
#pragma unroll
        for (int nt = 0; nt < 16; nt++) {
            float b0 = bias[m][nt * 8 + c0];
            float b1 = bias[m][nt * 8 + c0 + 1];
            acc[nt][0] = b0; acc[nt][1] = b1;
            acc[nt][2] = b0; acc[nt][3] = b1;
        }

#pragma unroll
        for (int kc = 0; kc < 16; kc++) {
            uint32_t al[4];
            ldmx4(al, sb + SM_X + aoff + kc * 32);
#pragma unroll
            for (int h = 0; h < 2; h++) {
                uint32_t Bh[4][4], Bl[4][4];
#pragma unroll
                for (int j = 0; j < 4; j++) {
                    uint32_t ro = (uint32_t)(h * 64 + j * 16) * XROW + kc * 32;
                    ldmx4(Bh[j], sb + SM_WH + boff + ro);
                    ldmx4(Bl[j], sb + SM_WL + boff + ro);
                }
#pragma unroll
                for (int j = 0; j < 4; j++) {
                    mma16816h(acc[h * 8 + 2 * j],     xh[kc], &Bh[j][0]);
                    mma16816h(acc[h * 8 + 2 * j + 1], xh[kc], &Bh[j][2]);
                }
#pragma unroll
                for (int j = 0; j < 4; j++) {
                    mma16816h(acc[h * 8 + 2 * j],     al, &Bh[j][0]);
                    mma16816h(acc[h * 8 + 2 * j + 1], al, &Bh[j][2]);
                }
#pragma unroll
                for (int j = 0; j < 4; j++) {
                    mma16816h(acc[h * 8 + 2 * j],     xh[kc], &Bl[j][0]);
                    mma16816h(acc[h * 8 + 2 * j + 1], xh[kc], &Bl[j][2]);
                }
            }
        }

        if (m < 2) {
            __half* D = (m == 0) ? g_Qh : g_Kh;
#pragma unroll
            for (int nt = 0; nt < 16; nt++) {
                int col = nt * 8 + c0;
                *(uint32_t*)(D + (size_t)r0 * PR_D + col)
                    = pack_f16x2(acc[nt][0], acc[nt][1]);
                *(uint32_t*)(D + (size_t)(r0 + 8) * PR_D + col)
                    = pack_f16x2(acc[nt][2], acc[nt][3]);
            }
        } else {
            __syncthreads();
            const int rl = 16 * w + (lane >> 2);
#pragma unroll
            for (int nt = 0; nt < 16; nt++) {
                int col = nt * 8 + c0;
                *(uint32_t*)(sm + rl * 272 + col * 2)
                    = pack_f16x2(acc[nt][0], acc[nt][1]);
                *(uint32_t*)(sm + (rl + 8) * 272 + col * 2)
                    = pack_f16x2(acc[nt][2], acc[nt][3]);
            }
            __syncthreads();
            const int d  = t >> 1;
            const int hf = t & 1;
            uint32_t u[32];
#pragma unroll
            for (int j = 0; j < 32; j++) {
                uint32_t a = *(const uint16_t*)(sm + (hf * 64 + 2 * j) * 272 + d * 2);
                uint32_t b = *(const uint16_t*)(sm + (hf * 64 + 2 * j + 1) * 272 + d * 2);
                u[j] = (b << 16) | a;
            }
            uint4* dst = (uint4*)(g_VTh + (size_t)d * PR_N + qb + hf * 64);
#pragma unroll
            for (int q = 0; q < 8; q++)
                dst[q] = make_uint4(u[4 * q], u[4 * q + 1], u[4 * q + 2], u[4 * q + 3]);
        }

        if (m < 2) {
            __syncthreads();
#pragma unroll
            for (int i = 0; i < 16; i++) {
                int cid = t + i * 256;
                int r = cid >> 5, c = cid & 31;
                size_t o = (size_t)(m + 1) * PR_D * PR_INDIM + (size_t)r * PR_INDIM + c * 8;
                cp16(sb + SM_WH + r * XROW + c * 16, g_WTh + o);
                cp16(sb + SM_WL + r * XROW + c * 16, g_WTl + o);
            }
            cp_commit();
            cp_wait0();
            __syncthreads();
        }
    }
}

// ---------------------------------------------------------------------------
// Kernel 2: HMMA flash attention, split-K x8, SINGLE-PASS S (q,k fp16).
// grid = 1024 (128 qt x 8 ks).  Epilogue: normalized fp16 partial O + (M,l).
// ---------------------------------------------------------------------------
#define KROW   272
#define VROW   144
#define OFF_K  0
#define OFF_V  17408
#define ST_BYTES 35840
#define SM_BYTES (4 * ST_BYTES)    // 143360

__device__ __forceinline__ void load_stage(uint32_t dst, int kb)
{
    const int t = threadIdx.x;
#pragma unroll
    for (int i = 0; i < 4; i++) {
        int cid = t + i * 256;
        int r = cid >> 4, c = cid & 15;
        cp16(dst + OFF_K + r * KROW + c * 16, g_Kh + (size_t)(kb + r) * PR_D + c * 8);
    }
#pragma unroll
    for (int i = 0; i < 4; i++) {
        int cid = t + i * 256;
        int r = cid >> 3, c = cid & 7;
        cp16(dst + OFF_V + r * VROW + c * 16, g_VTh + (size_t)r * PR_N + kb + c * 8);
    }
}

__global__ void __launch_bounds__(256, 1) pr_attn_mma()
{
    extern __shared__ char sm[];
    const uint32_t sb = smem_u32(sm);

    const int t     = threadIdx.x;
    const int w     = t >> 5;
    const int lane  = t & 31;
    const int qb    = (blockIdx.x >> 3) * 128;
    const int ks    = blockIdx.x & 7;
    const int kbase = ks * KEYS_PER;

    const uint32_t aRow = (uint32_t)(16 * w + (lane & 15));
    const uint32_t aCol = (uint32_t)(lane >> 4);
    const uint32_t bRow = (uint32_t)((lane & 7) + 8 * (lane >> 4));
    const uint32_t bCol = (uint32_t)((lane >> 3) & 1);
    const uint32_t bKoff = bRow * KROW + bCol * 16;
    const uint32_t bVoff = bRow * VROW + bCol * 16;

    // ---- stage Q (single fp16) and grab fragments ----
    {
#pragma unroll
        for (int i = 0; i < 8; i++) {
            int cid = t + i * 256;
            int r = cid >> 4, c = cid & 15;
            cp16(sb + r * KROW + c * 16, g_Qh + (size_t)(qb + r) * PR_D + c * 8);
        }
        cp_commit();
        cp_wait0();
        __syncthreads();
    }
    uint32_t qh[8][4];
    {
        const uint32_t aQ = sb + aRow * KROW + aCol * 16;
#pragma unroll
        for (int kc = 0; kc < 8; kc++)
            ldmx4(qh[kc], aQ + kc * 32);
    }
    __syncthreads();

    float o[16][4];
#pragma unroll
    for (int i = 0; i < 16; i++)
#pragma unroll
        for (int j = 0; j < 4; j++) o[i][j] = 0.0f;
    float lsum0 = 0.0f, lsum1 = 0.0f;
    float M0 = -1e30f, M1 = -1e30f;

    load_stage(sb + 0 * ST_BYTES, kbase);
    cp_commit();
    load_stage(sb + 1 * ST_BYTES, kbase + 64);
    cp_commit();
    load_stage(sb + 2 * ST_BYTES, kbase + 128);
    cp_commit();

    int st_cur = 0, st_pre = 3;
#pragma unroll 1
    for (int tt = 0; tt < NTS; tt++) {
        __syncthreads();
        if (tt + 3 < NTS) load_stage(sb + st_pre * ST_BYTES, kbase + (tt + 3) * 64);
        cp_commit();
        cp_wait2();
        __syncthreads();

        const uint32_t p   = sb + st_cur * ST_BYTES;
        const uint32_t bKh = p + OFF_K + bKoff;
        const uint32_t bVh = p + OFF_V + bVoff;

        // ---- S = Q K^T single pass, 64 keys ----
        float s[8][4];
#pragma unroll
        for (int i = 0; i < 8; i++)
#pragma unroll
            for (int j = 0; j < 4; j++) s[i][j] = 0.0f;

#pragma unroll
        for (int kc = 0; kc < 8; kc++) {
            uint32_t bh[4][4];
#pragma unroll
            for (int jn = 0; jn < 4; jn++)
                ldmx4(bh[jn], bKh + jn * (16 * KROW) + kc * 32);
#pragma unroll
            for (int jn = 0; jn < 4; jn++) {
                mma16816h(s[2 * jn],     qh[kc], &bh[jn][0]);
                mma16816h(s[2 * jn + 1], qh[kc], &bh[jn][2]);
            }
        }

        // ---- flash softmax: running max, rescale only on max increase ----
        float m0 = s[0][0], m1 = s[0][2];
#pragma unroll
        for (int jt = 0; jt < 8; jt++) {
            m0 = fmaxf(m0, fmaxf(s[jt][0], s[jt][1]));
            m1 = fmaxf(m1, fmaxf(s[jt][2], s[jt][3]));
        }
        m0 = fmaxf(m0, __shfl_xor_sync(0xffffffffu, m0, 1));
        m0 = fmaxf(m0, __shfl_xor_sync(0xffffffffu, m0, 2));
        m1 = fmaxf(m1, __shfl_xor_sync(0xffffffffu, m1, 1));
        m1 = fmaxf(m1, __shfl_xor_sync(0xffffffffu, m1, 2));

        if (m0 > M0 || m1 > M1) {
            const float M0n = fmaxf(M0, m0), M1n = fmaxf(M1, m1);
            const float sc0 = ex2f((M0 - M0n) * LOG2E);
            const float sc1 = ex2f((M1 - M1n) * LOG2E);
            M0 = M0n; M1 = M1n;
            lsum0 *= sc0;
            lsum1 *= sc1;
#pragma unroll
            for (int dt = 0; dt < 16; dt++) {
                o[dt][0] *= sc0; o[dt][1] *= sc0;
                o[dt][2] *= sc1; o[dt][3] *= sc1;
            }
        }
        const float b0 = M0 * LOG2E, b1 = M1 * LOG2E;

        float ts0 = 0.0f, ts1 = 0.0f;
        uint32_t pp[16];
#pragma unroll
        for (int jt = 0; jt < 8; jt++) {
            float e0 = ex2f(fmaf(s[jt][0], LOG2E, -b0));
            float e1 = ex2f(fmaf(s[jt][1], LOG2E, -b0));
            float e2 = ex2f(fmaf(s[jt][2], LOG2E, -b1));
            float e3 = ex2f(fmaf(s[jt][3], LOG2E, -b1));
            ts0 += e0 + e1;
            ts1 += e2 + e3;
            pp[2 * jt]     = pack_f16x2(e0, e1);
            pp[2 * jt + 1] = pack_f16x2(e2, e3);
        }
        lsum0 += ts0;
        lsum1 += ts1;

        // ---- O += P V (single-pass fp16) ----
        uint32_t v[2][4];
        ldmx4(v[0], bVh);
#pragma unroll
        for (int idx = 0; idx < 32; idx++) {
            const int cur = idx & 1, nxt = cur ^ 1;
            if (idx < 31) {
                const int kc2 = (idx + 1) >> 3, dn2 = (idx + 1) & 7;
                ldmx4(v[nxt], bVh + dn2 * (16 * VROW) + kc2 * 32);
            }
            const int kc = idx >> 3, dn = idx & 7;
            mma16816h(o[2 * dn],     &pp[4 * kc], &v[cur][0]);
            mma16816h(o[2 * dn + 1], &pp[4 * kc], &v[cur][2]);
        }

        st_cur = (st_cur + 1) & 3;
        st_pre = (st_pre + 1) & 3;
    }

    // ---- epilogue: normalize, write fp16 partials + (M, lsum) ----
    lsum0 += __shfl_xor_sync(0xffffffffu, lsum0, 1);
    lsum0 += __shfl_xor_sync(0xffffffffu, lsum0, 2);
    lsum1 += __shfl_xor_sync(0xffffffffu, lsum1, 1);
    lsum1 += __shfl_xor_sync(0xffffffffu, lsum1, 2);
    const float inv0 = 1.0f / lsum0;
    const float inv1 = 1.0f / lsum1;

    const int r0 = qb + 16 * w + (lane >> 2);
    const int cb = 2 * (lane & 3);
    __half* pO = g_pO + ((size_t)ks * PR_N) * PR_D;
#pragma unroll
    for (int dt = 0; dt < 16; dt++) {
        *(uint32_t*)(pO + (size_t)r0 * PR_D + 8 * dt + cb)
            = pack_f16x2(o[dt][0] * inv0, o[dt][1] * inv0);
        *(uint32_t*)(pO + (size_t)(r0 + 8) * PR_D + 8 * dt + cb)
            = pack_f16x2(o[dt][2] * inv1, o[dt][3] * inv1);
    }
    if ((lane & 3) == 0) {
        g_pM[ks * PR_N + r0]     = M0;
        g_pL[ks * PR_N + r0]     = lsum0;
        g_pM[ks * PR_N + r0 + 8] = M1;
        g_pL[ks * PR_N + r0 + 8] = lsum1;
    }
}

// ---------------------------------------------------------------------------
// Kernel 3: merge 8 normalized fp16 partials.  grid=1024 x 256.
// thread -> (row, 8-col chunk): 16384 rows x 16 chunks.
// ---------------------------------------------------------------------------
__global__ void __launch_bounds__(256) pr_merge(float* __restrict__ out)
{
    const int g   = blockIdx.x * 256 + threadIdx.x;   // 262144
    const int row = g >> 4;
    const int c8  = (g & 15) * 8;

    float M = -1e30f;
#pragma unroll
    for (int i = 0; i < KSPLIT; i++)
        M = fmaxf(M, g_pM[i * PR_N + row]);

    float wsum = 0.0f;
    float acc[8];
#pragma unroll
    for (int j = 0; j < 8; j++) acc[j] = 0.0f;

#pragma unroll
    for (int i = 0; i < KSPLIT; i++) {
        float wgt = g_pL[i * PR_N + row] * ex2f((g_pM[i * PR_N + row] - M) * LOG2E);
        wsum += wgt;
        uint4 raw = *(const uint4*)(g_pO + ((size_t)i * PR_N + row) * PR_D + c8);
        const uint32_t* rw = &raw.x;
#pragma unroll
        for (int j = 0; j < 4; j++) {
            float2 v = __half22float2(*(const __half2*)&rw[j]);
            acc[2 * j]     = fmaf(v.x, wgt, acc[2 * j]);
            acc[2 * j + 1] = fmaf(v.y, wgt, acc[2 * j + 1]);
        }
    }
    const float inv = 1.0f / wsum;
    float4 o0, o1;
    o0.x = acc[0] * inv; o0.y = acc[1] * inv;
    o0.z = acc[2] * inv; o0.w = acc[3] * inv;
    o1.x = acc[4] * inv; o1.y = acc[5] * inv;
    o1.z = acc[6] * inv; o1.w = acc[7] * inv;
    float4* dst = (float4*)(out + (size_t)row * PR_D + c8);
    dst[0] = o0;
    dst[1] = o1;
}

// ---------------------------------------------------------------------------
extern "C" void kernel_launch(void* const* d_in, const int* in_sizes, int n_in,
                              void* d_out, int out_size)
{
    const float* x  = (const float*)d_in[0];
    const float* Wq = (const float*)d_in[1];
    const float* bq = (const float*)d_in[2];
    const float* Wk = (const float*)d_in[3];
    const float* bk = (const float*)d_in[4];
    const float* Wv = (const float*)d_in[5];
    const float* bv = (const float*)d_in[6];
    float* out = (float*)d_out;

    pr_convert<<<2096, 256>>>(x, Wq, Wk, Wv);

    cudaFuncSetAttribute(pr_proj_mma,
                         cudaFuncAttributeMaxDynamicSharedMemorySize, PROJ_SM);
    pr_proj_mma<<<PR_N / 128, 256, PROJ_SM>>>(bq, bk, bv);

    cudaFuncSetAttribute(pr_attn_mma,
                         cudaFuncAttributeMaxDynamicSharedMemorySize, SM_BYTES);
    pr_attn_mma<<<(PR_N / 128) * KSPLIT, 256, SM_BYTES>>>();

    pr_merge<<<1024, 256>>>(out);
}

// round 15
// speedup vs baseline: 1.9051x; 1.0283x over previous
#include <cuda_runtime.h>
#include <cuda_fp16.h>
#include <cstdint>
#include <cstddef>

#define PR_N      16384
#define PR_INDIM  256
#define PR_D      128
#define LOG2E     1.4426950408889634f
#define KSPLIT    8
#define KEYS_PER  (PR_N / KSPLIT)      // 2048
#define NTS       (KEYS_PER / 64)      // 32 subtiles per CTA

// ---------------- scratch ---------------------------------------------------
__device__ __align__(16) __half g_Qh [PR_N * PR_D];
__device__ __align__(16) __half g_Kh [PR_N * PR_D];
__device__ __align__(16) __half g_VTh[PR_D * PR_N];        // V^T [d][n]
__device__ __align__(16) __half g_xh [PR_N * PR_INDIM];
__device__ __align__(16) __half g_xl [PR_N * PR_INDIM];
__device__ __align__(16) __half g_WTh[3 * PR_D * PR_INDIM];
__device__ __align__(16) __half g_WTl[3 * PR_D * PR_INDIM];
// split-K partials (O normalized per split, stored fp16)
__device__ __align__(16) __half g_pO[KSPLIT * PR_N * PR_D];  // 32 MB
__device__ __align__(16) float  g_pM[KSPLIT * PR_N];
__device__ __align__(16) float  g_pL[KSPLIT * PR_N];

// ---------------- helpers ---------------------------------------------------
__device__ __forceinline__ uint32_t smem_u32(const void* p) {
    uint32_t a;
    asm("{ .reg .u64 t; cvta.to.shared.u64 t, %1; cvt.u32.u64 %0, t; }"
        : "=r"(a) : "l"(p));
    return a;
}
__device__ __forceinline__ float ex2f(float x) {
    float r;
    asm("ex2.approx.ftz.f32 %0, %1;" : "=f"(r) : "f"(x));
    return r;
}
__device__ __forceinline__ uint32_t pack_f16x2(float a, float b) {
    uint32_t r;
    asm("cvt.rn.f16x2.f32 %0, %1, %2;" : "=r"(r) : "f"(b), "f"(a));
    return r;
}
__device__ __forceinline__ void split2h(float f0, float f1, uint32_t& hi, uint32_t& lo) {
    __half a0 = __float2half_rn(f0), a1 = __float2half_rn(f1);
    hi = ((uint32_t)__half_as_ushort(a1) << 16) | __half_as_ushort(a0);
    lo = pack_f16x2(f0 - __half2float(a0), f1 - __half2float(a1));
}
__device__ __forceinline__ void ldmx4(uint32_t* r, uint32_t addr) {
    asm volatile("ldmatrix.sync.aligned.m8n8.x4.shared.b16 {%0,%1,%2,%3}, [%4];"
                 : "=r"(r[0]), "=r"(r[1]), "=r"(r[2]), "=r"(r[3]) : "r"(addr));
}
__device__ __forceinline__ void mma16816h(float* c, const uint32_t* a,
                                          const uint32_t* b) {
    asm volatile(
        "mma.sync.aligned.m16n8k16.row.col.f32.f16.f16.f32 "
        "{%0,%1,%2,%3}, {%4,%5,%6,%7}, {%8,%9}, {%0,%1,%2,%3};"
        : "+f"(c[0]), "+f"(c[1]), "+f"(c[2]), "+f"(c[3])
        : "r"(a[0]), "r"(a[1]), "r"(a[2]), "r"(a[3]), "r"(b[0]), "r"(b[1]));
}
__device__ __forceinline__ void cp16(uint32_t dst, const void* src) {
    asm volatile("cp.async.cg.shared.global [%0], [%1], 16;"
                 :: "r"(dst), "l"(src) : "memory");
}
__device__ __forceinline__ void cp_commit() {
    asm volatile("cp.async.commit_group;" ::: "memory");
}
__device__ __forceinline__ void cp_wait1() {
    asm volatile("cp.async.wait_group 1;" ::: "memory");
}
__device__ __forceinline__ void cp_wait0() {
    asm volatile("cp.async.wait_group 0;" ::: "memory");
}

// ---------------------------------------------------------------------------
// Kernel 0: convert x -> fp16 hi/lo; W -> W^T fp16 hi/lo.
// ---------------------------------------------------------------------------
__global__ void __launch_bounds__(256) pr_convert(
    const float* __restrict__ x,
    const float* __restrict__ Wq, const float* __restrict__ Wk,
    const float* __restrict__ Wv)
{
    const int bid = blockIdx.x, t = threadIdx.x;
    if (bid < 2048) {
        size_t e0 = ((size_t)bid * 256 + t) * 8;
        float4 f0 = *(const float4*)(x + e0);
        float4 f1 = *(const float4*)(x + e0 + 4);
        uint32_t h[4], l[4];
        split2h(f0.x, f0.y, h[0], l[0]);
        split2h(f0.z, f0.w, h[1], l[1]);
        split2h(f1.x, f1.y, h[2], l[2]);
        split2h(f1.z, f1.w, h[3], l[3]);
        *(uint4*)(g_xh + e0) = make_uint4(h[0], h[1], h[2], h[3]);
        *(uint4*)(g_xl + e0) = make_uint4(l[0], l[1], l[2], l[3]);
    } else {
        int idx = (bid - 2048) * 256 + t;
        int m   = idx >> 12;
        int rem = idx & 4095;
        int d   = rem >> 5;
        int k0  = (rem & 31) * 8;
        const float* W = (m == 0) ? Wq : ((m == 1) ? Wk : Wv);
        uint32_t h[4], l[4];
#pragma unroll
        for (int i = 0; i < 4; i++) {
            float a = W[(size_t)(k0 + 2 * i) * PR_D + d];
            float b = W[(size_t)(k0 + 2 * i + 1) * PR_D + d];
            split2h(a, b, h[i], l[i]);
        }
        size_t o = ((size_t)m * PR_D + d) * PR_INDIM + k0;
        *(uint4*)(g_WTh + o) = make_uint4(h[0], h[1], h[2], h[3]);
        *(uint4*)(g_WTl + o) = make_uint4(l[0], l[1], l[2], l[3]);
    }
}

// ---------------------------------------------------------------------------
// Kernel 1: HMMA projection, 3-pass split fp16 (unchanged from R14).
// ---------------------------------------------------------------------------
#define XROW    528
#define SM_X    0
#define SM_WH   67584
#define SM_WL   135168
#define PROJ_SM 202752

__global__ void __launch_bounds__(256, 1) pr_proj_mma(
    const float* __restrict__ bq, const float* __restrict__ bk,
    const float* __restrict__ bv)
{
    extern __shared__ char sm[];
    const uint32_t sb = smem_u32(sm);

    const int t    = threadIdx.x;
    const int w    = t >> 5;
    const int lane = t & 31;
    const int qb   = blockIdx.x * 128;

    const uint32_t aoff = (uint32_t)(16 * w + (lane & 15)) * XROW
                        + (uint32_t)(lane >> 4) * 16;
    const uint32_t boff = (uint32_t)((lane & 7) + 8 * (lane >> 4)) * XROW
                        + (uint32_t)((lane >> 3) & 1) * 16;

#pragma unroll
    for (int i = 0; i < 16; i++) {
        int cid = t + i * 256;
        int r = cid >> 5, c = cid & 31;
        cp16(sb + SM_X + r * XROW + c * 16, g_xh + (size_t)(qb + r) * PR_INDIM + c * 8);
    }
    cp_commit();
    cp_wait0();
    __syncthreads();

    uint32_t xh[16][4];
#pragma unroll
    for (int kc = 0; kc < 16; kc++)
        ldmx4(xh[kc], sb + SM_X + aoff + kc * 32);
    __syncthreads();

#pragma unroll
    for (int i = 0; i < 16; i++) {
        int cid = t + i * 256;
        int r = cid >> 5, c = cid & 31;
        cp16(sb + SM_X + r * XROW + c * 16, g_xl + (size_t)(qb + r) * PR_INDIM + c * 8);
        cp16(sb + SM_WH + r * XROW + c * 16, g_WTh + (size_t)r * PR_INDIM + c * 8);
        cp16(sb + SM_WL + r * XROW + c * 16, g_WTl + (size_t)r * PR_INDIM + c * 8);
    }
    cp_commit();
    cp_wait0();
    __syncthreads();

    const float* bias[3] = {bq, bk, bv};
    const int r0 = qb + 16 * w + (lane >> 2);
    const int c0 = 2 * (lane & 3);

#pragma unroll 1
    for (int m = 0; m < 3; m++) {
        float acc[16][4];
#pragma unroll
        for (int nt = 0; nt < 16; nt++) {
            float b0 = bias[m][nt * 8 + c0];
            float b1 = bias[m][nt * 8 + c0 + 1];
            acc[nt][0] = b0; acc[nt][1] = b1;
            acc[nt][2] = b0; acc[nt][3] = b1;
        }

#pragma unroll
        for (int kc = 0; kc < 16; kc++) {
            uint32_t al[4];
            ldmx4(al, sb + SM_X + aoff + kc * 32);
#pragma unroll
            for (int h = 0; h < 2; h++) {
                uint32_t Bh[4][4], Bl[4][4];
#pragma unroll
                for (int j = 0; j < 4; j++) {
                    uint32_t ro = (uint32_t)(h * 64 + j * 16) * XROW + kc * 32;
                    ldmx4(Bh[j], sb + SM_WH + boff + ro);
                    ldmx4(Bl[j], sb + SM_WL + boff + ro);
                }
#pragma unroll
                for (int j = 0; j < 4; j++) {
                    mma16816h(acc[h * 8 + 2 * j],     xh[kc], &Bh[j][0]);
                    mma16816h(acc[h * 8 + 2 * j + 1], xh[kc], &Bh[j][2]);
                }
#pragma unroll
                for (int j = 0; j < 4; j++) {
                    mma16816h(acc[h * 8 + 2 * j],     al, &Bh[j][0]);
                    mma16816h(acc[h * 8 + 2 * j + 1], al, &Bh[j][2]);
                }
#pragma unroll
                for (int j = 0; j < 4; j++) {
                    mma16816h(acc[h * 8 + 2 * j],     xh[kc], &Bl[j][0]);
                    mma16816h(acc[h * 8 + 2 * j + 1], xh[kc], &Bl[j][2]);
                }
            }
        }

        if (m < 2) {
            __half* D = (m == 0) ? g_Qh : g_Kh;
#pragma unroll
            for (int nt = 0; nt < 16; nt++) {
                int col = nt * 8 + c0;
                *(uint32_t*)(D + (size_t)r0 * PR_D + col)
                    = pack_f16x2(acc[nt][0], acc[nt][1]);
                *(uint32_t*)(D + (size_t)(r0 + 8) * PR_D + col)
                    = pack_f16x2(acc[nt][2], acc[nt][3]);
            }
        } else {
            __syncthreads();
            const int rl = 16 * w + (lane >> 2);
#pragma unroll
            for (int nt = 0; nt < 16; nt++) {
                int col = nt * 8 + c0;
                *(uint32_t*)(sm + rl * 272 + col * 2)
                    = pack_f16x2(acc[nt][0], acc[nt][1]);
                *(uint32_t*)(sm + (rl + 8) * 272 + col * 2)
                    = pack_f16x2(acc[nt][2], acc[nt][3]);
            }
            __syncthreads();
            const int d  = t >> 1;
            const int hf = t & 1;
            uint32_t u[32];
#pragma unroll
            for (int j = 0; j < 32; j++) {
                uint32_t a = *(const uint16_t*)(sm + (hf * 64 + 2 * j) * 272 + d * 2);
                uint32_t b = *(const uint16_t*)(sm + (hf * 64 + 2 * j + 1) * 272 + d * 2);
                u[j] = (b << 16) | a;
            }
            uint4* dst = (uint4*)(g_VTh + (size_t)d * PR_N + qb + hf * 64);
#pragma unroll
            for (int q = 0; q < 8; q++)
                dst[q] = make_uint4(u[4 * q], u[4 * q + 1], u[4 * q + 2], u[4 * q + 3]);
        }

        if (m < 2) {
            __syncthreads();
#pragma unroll
            for (int i = 0; i < 16; i++) {
                int cid = t + i * 256;
                int r = cid >> 5, c = cid & 31;
                size_t o = (size_t)(m + 1) * PR_D * PR_INDIM + (size_t)r * PR_INDIM + c * 8;
                cp16(sb + SM_WH + r * XROW + c * 16, g_WTh + o);
                cp16(sb + SM_WL + r * XROW + c * 16, g_WTl + o);
            }
            cp_commit();
            cp_wait0();
            __syncthreads();
        }
    }
}

// ---------------------------------------------------------------------------
// Kernel 2: HMMA flash attention, split-K x8, 2 CTAs/SM.
// CTA = 128 threads (4 warps), 64 q-rows.  grid = 2048 (256 qt x 8 ks).
// 3 smem stages, ONE barrier per subtile (wait-own-groups -> barrier -> load).
// ---------------------------------------------------------------------------
#define ATH    128                 // attn CTA threads
#define KROW   272
#define VROW   144
#define OFF_K  0
#define OFF_V  17408
#define ST_BYTES 35840
#define SM_BYTES (3 * ST_BYTES)    // 107520

__device__ __forceinline__ void load_stage(uint32_t dst, int kb)
{
    const int t = threadIdx.x;
#pragma unroll
    for (int i = 0; i < 8; i++) {
        int cid = t + i * ATH;               // 1024: 64 rows x 16 chunks
        int r = cid >> 4, c = cid & 15;
        cp16(dst + OFF_K + r * KROW + c * 16, g_Kh + (size_t)(kb + r) * PR_D + c * 8);
    }
#pragma unroll
    for (int i = 0; i < 8; i++) {
        int cid = t + i * ATH;               // 1024: 128 d x 8 chunks
        int r = cid >> 3, c = cid & 7;
        cp16(dst + OFF_V + r * VROW + c * 16, g_VTh + (size_t)r * PR_N + kb + c * 8);
    }
}

__global__ void __launch_bounds__(ATH, 2) pr_attn_mma()
{
    extern __shared__ char sm[];
    const uint32_t sb = smem_u32(sm);

    const int t     = threadIdx.x;
    const int w     = t >> 5;          // 0..3
    const int lane  = t & 31;
    const int qb    = (blockIdx.x >> 3) * 64;
    const int ks    = blockIdx.x & 7;
    const int kbase = ks * KEYS_PER;

    const uint32_t aRow = (uint32_t)(16 * w + (lane & 15));
    const uint32_t aCol = (uint32_t)(lane >> 4);
    const uint32_t bRow = (uint32_t)((lane & 7) + 8 * (lane >> 4));
    const uint32_t bCol = (uint32_t)((lane >> 3) & 1);
    const uint32_t bKoff = bRow * KROW + bCol * 16;
    const uint32_t bVoff = bRow * VROW + bCol * 16;

    // ---- stage Q (64 rows, single fp16) into stage-0 area, grab fragments ----
    {
#pragma unroll
        for (int i = 0; i < 8; i++) {
            int cid = t + i * ATH;           // 1024: 64 rows x 16 chunks
            int r = cid >> 4, c = cid & 15;
            cp16(sb + r * KROW + c * 16, g_Qh + (size_t)(qb + r) * PR_D + c * 8);
        }
        cp_commit();
        cp_wait0();
        __syncthreads();
    }
    uint32_t qh[8][4];
    {
        const uint32_t aQ = sb + aRow * KROW + aCol * 16;
#pragma unroll
        for (int kc = 0; kc < 8; kc++)
            ldmx4(qh[kc], aQ + kc * 32);
    }
    __syncthreads();                         // frags read before stage-0 overwrite

    float o[16][4];
#pragma unroll
    for (int i = 0; i < 16; i++)
#pragma unroll
        for (int j = 0; j < 4; j++) o[i][j] = 0.0f;
    float lsum0 = 0.0f, lsum1 = 0.0f;
    float M0 = -1e30f, M1 = -1e30f;

    // prologue: tiles 0,1
    load_stage(sb + 0 * ST_BYTES, kbase);
    cp_commit();
    load_stage(sb + 1 * ST_BYTES, kbase + 64);
    cp_commit();

    int st_cur = 0, st_pre = 2;
#pragma unroll 1
    for (int tt = 0; tt < NTS; tt++) {
        cp_wait1();                  // own groups: tile tt landed (through tt+1 issued)
        __syncthreads();             // all threads' tt visible; all done with tt-1
        if (tt + 2 < NTS) load_stage(sb + st_pre * ST_BYTES, kbase + (tt + 2) * 64);
        cp_commit();                 // commit every iter (keeps group FIFO aligned)

        const uint32_t p   = sb + st_cur * ST_BYTES;
        const uint32_t bKh = p + OFF_K + bKoff;
        const uint32_t bVh = p + OFF_V + bVoff;

        // ---- S = Q K^T single pass, 64 keys ----
        float s[8][4];
#pragma unroll
        for (int i = 0; i < 8; i++)
#pragma unroll
            for (int j = 0; j < 4; j++) s[i][j] = 0.0f;

#pragma unroll
        for (int kc = 0; kc < 8; kc++) {
            uint32_t bh[4][4];
#pragma unroll
            for (int jn = 0; jn < 4; jn++)
                ldmx4(bh[jn], bKh + jn * (16 * KROW) + kc * 32);
#pragma unroll
            for (int jn = 0; jn < 4; jn++) {
                mma16816h(s[2 * jn],     qh[kc], &bh[jn][0]);
                mma16816h(s[2 * jn + 1], qh[kc], &bh[jn][2]);
            }
        }

        // ---- flash softmax: running max, rescale only on max increase ----
        float m0 = s[0][0], m1 = s[0][2];
#pragma unroll
        for (int jt = 0; jt < 8; jt++) {
            m0 = fmaxf(m0, fmaxf(s[jt][0], s[jt][1]));
            m1 = fmaxf(m1, fmaxf(s[jt][2], s[jt][3]));
        }
        m0 = fmaxf(m0, __shfl_xor_sync(0xffffffffu, m0, 1));
        m0 = fmaxf(m0, __shfl_xor_sync(0xffffffffu, m0, 2));
        m1 = fmaxf(m1, __shfl_xor_sync(0xffffffffu, m1, 1));
        m1 = fmaxf(m1, __shfl_xor_sync(0xffffffffu, m1, 2));

        if (m0 > M0 || m1 > M1) {
            const float M0n = fmaxf(M0, m0), M1n = fmaxf(M1, m1);
            const float sc0 = ex2f((M0 - M0n) * LOG2E);
            const float sc1 = ex2f((M1 - M1n) * LOG2E);
            M0 = M0n; M1 = M1n;
            lsum0 *= sc0;
            lsum1 *= sc1;
#pragma unroll
            for (int dt = 0; dt < 16; dt++) {
                o[dt][0] *= sc0; o[dt][1] *= sc0;
                o[dt][2] *= sc1; o[dt][3] *= sc1;
            }
        }
        const float b0 = M0 * LOG2E, b1 = M1 * LOG2E;

        float ts0 = 0.0f, ts1 = 0.0f;
        uint32_t pp[16];
#pragma unroll
        for (int jt = 0; jt < 8; jt++) {
            float e0 = ex2f(fmaf(s[jt][0], LOG2E, -b0));
            float e1 = ex2f(fmaf(s[jt][1], LOG2E, -b0));
            float e2 = ex2f(fmaf(s[jt][2], LOG2E, -b1));
            float e3 = ex2f(fmaf(s[jt][3], LOG2E, -b1));
            ts0 += e0 + e1;
            ts1 += e2 + e3;
            pp[2 * jt]     = pack_f16x2(e0, e1);
            pp[2 * jt + 1] = pack_f16x2(e2, e3);
        }
        lsum0 += ts0;
        lsum1 += ts1;

        // ---- O += P V (single-pass fp16) ----
        uint32_t v[2][4];
        ldmx4(v[0], bVh);
#pragma unroll
        for (int idx = 0; idx < 32; idx++) {
            const int cur = idx & 1, nxt = cur ^ 1;
            if (idx < 31) {
                const int kc2 = (idx + 1) >> 3, dn2 = (idx + 1) & 7;
                ldmx4(v[nxt], bVh + dn2 * (16 * VROW) + kc2 * 32);
            }
            const int kc = idx >> 3, dn = idx & 7;
            mma16816h(o[2 * dn],     &pp[4 * kc], &v[cur][0]);
            mma16816h(o[2 * dn + 1], &pp[4 * kc], &v[cur][2]);
        }

        st_cur = (st_cur == 2) ? 0 : st_cur + 1;
        st_pre = (st_pre == 2) ? 0 : st_pre + 1;
    }

    // ---- epilogue: normalize, write fp16 partials + (M, lsum) ----
    lsum0 += __shfl_xor_sync(0xffffffffu, lsum0, 1);
    lsum0 += __shfl_xor_sync(0xffffffffu, lsum0, 2);
    lsum1 += __shfl_xor_sync(0xffffffffu, lsum1, 1);
    lsum1 += __shfl_xor_sync(0xffffffffu, lsum1, 2);
    const float inv0 = 1.0f / lsum0;
    const float inv1 = 1.0f / lsum1;

    const int r0 = qb + 16 * w + (lane >> 2);
    const int cb = 2 * (lane & 3);
    __half* pO = g_pO + ((size_t)ks * PR_N) * PR_D;
#pragma unroll
    for (int dt = 0; dt < 16; dt++) {
        *(uint32_t*)(pO + (size_t)r0 * PR_D + 8 * dt + cb)
            = pack_f16x2(o[dt][0] * inv0, o[dt][1] * inv0);
        *(uint32_t*)(pO + (size_t)(r0 + 8) * PR_D + 8 * dt + cb)
            = pack_f16x2(o[dt][2] * inv1, o[dt][3] * inv1);
    }
    if ((lane & 3) == 0) {
        g_pM[ks * PR_N + r0]     = M0;
        g_pL[ks * PR_N + r0]     = lsum0;
        g_pM[ks * PR_N + r0 + 8] = M1;
        g_pL[ks * PR_N + r0 + 8] = lsum1;
    }
}

// ---------------------------------------------------------------------------
// Kernel 3: merge 8 normalized fp16 partials.  grid=1024 x 256.
// ---------------------------------------------------------------------------
__global__ void __launch_bounds__(256) pr_merge(float* __restrict__ out)
{
    const int g   = blockIdx.x * 256 + threadIdx.x;   // 262144
    const int row = g >> 4;
    const int c8  = (g & 15) * 8;

    float M = -1e30f;
#pragma unroll
    for (int i = 0; i < KSPLIT; i++)
        M = fmaxf(M, g_pM[i * PR_N + row]);

    float wsum = 0.0f;
    float acc[8];
#pragma unroll
    for (int j = 0; j < 8; j++) acc[j] = 0.0f;

#pragma unroll
    for (int i = 0; i < KSPLIT; i++) {
        float wgt = g_pL[i * PR_N + row] * ex2f((g_pM[i * PR_N + row] - M) * LOG2E);
        wsum += wgt;
        uint4 raw = *(const uint4*)(g_pO + ((size_t)i * PR_N + row) * PR_D + c8);
        const uint32_t* rw = &raw.x;
#pragma unroll
        for (int j = 0; j < 4; j++) {
            float2 v = __half22float2(*(const __half2*)&rw[j]);
            acc[2 * j]     = fmaf(v.x, wgt, acc[2 * j]);
            acc[2 * j + 1] = fmaf(v.y, wgt, acc[2 * j + 1]);
        }
    }
    const float inv = 1.0f / wsum;
    float4 o0, o1;
    o0.x = acc[0] * inv; o0.y = acc[1] * inv;
    o0.z = acc[2] * inv; o0.w = acc[3] * inv;
    o1.x = acc[4] * inv; o1.y = acc[5] * inv;
    o1.z = acc[6] * inv; o1.w = acc[7] * inv;
    float4* dst = (float4*)(out + (size_t)row * PR_D + c8);
    dst[0] = o0;
    dst[1] = o1;
}

// ---------------------------------------------------------------------------
extern "C" void kernel_launch(void* const* d_in, const int* in_sizes, int n_in,
                              void* d_out, int out_size)
{
    const float* x  = (const float*)d_in[0];
    const float* Wq = (const float*)d_in[1];
    const float* bq = (const float*)d_in[2];
    const float* Wk = (const float*)d_in[3];
    const float* bk = (const float*)d_in[4];
    const float* Wv = (const float*)d_in[5];
    const float* bv = (const float*)d_in[6];
    float* out = (float*)d_out;

    pr_convert<<<2096, 256>>>(x, Wq, Wk, Wv);

    cudaFuncSetAttribute(pr_proj_mma,
                         cudaFuncAttributeMaxDynamicSharedMemorySize, PROJ_SM);
    pr_proj_mma<<<PR_N / 128, 256, PROJ_SM>>>(bq, bk, bv);

    cudaFuncSetAttribute(pr_attn_mma,
                         cudaFuncAttributeMaxDynamicSharedMemorySize, SM_BYTES);
    pr_attn_mma<<<(PR_N / 64) * KSPLIT, ATH, SM_BYTES>>>();

    pr_merge<<<1024, 256>>>(out);
}

// round 16
// speedup vs baseline: 2.0210x; 1.0608x over previous
#include <cuda_runtime.h>
#include <cuda_fp16.h>
#include <cstdint>
#include <cstddef>

#define PR_N      16384
#define PR_INDIM  256
#define PR_D      128
#define LOG2E     1.4426950408889634f
#define KSPLIT    16
#define KEYS_PER  (PR_N / KSPLIT)      // 1024
#define NTS       (KEYS_PER / 64)      // 16 subtiles per CTA

// ---------------- scratch ---------------------------------------------------
__device__ __align__(16) __half g_Qh [PR_N * PR_D];
__device__ __align__(16) __half g_Kh [PR_N * PR_D];
__device__ __align__(16) __half g_VTh[PR_D * PR_N];        // V^T [d][n]
__device__ __align__(16) __half g_xh [PR_N * PR_INDIM];
__device__ __align__(16) __half g_xl [PR_N * PR_INDIM];
__device__ __align__(16) __half g_WTh[3 * PR_D * PR_INDIM];
__device__ __align__(16) __half g_WTl[3 * PR_D * PR_INDIM];
// split-K partials (O normalized per split, stored fp16)
__device__ __align__(16) __half g_pO[KSPLIT * PR_N * PR_D];  // 64 MB
__device__ __align__(16) float  g_pM[KSPLIT * PR_N];
__device__ __align__(16) float  g_pL[KSPLIT * PR_N];

// ---------------- helpers ---------------------------------------------------
__device__ __forceinline__ uint32_t smem_u32(const void* p) {
    uint32_t a;
    asm("{ .reg .u64 t; cvta.to.shared.u64 t, %1; cvt.u32.u64 %0, t; }"
        : "=r"(a) : "l"(p));
    return a;
}
__device__ __forceinline__ float ex2f(float x) {
    float r;
    asm("ex2.approx.ftz.f32 %0, %1;" : "=f"(r) : "f"(x));
    return r;
}
__device__ __forceinline__ uint32_t pack_f16x2(float a, float b) {
    uint32_t r;
    asm("cvt.rn.f16x2.f32 %0, %1, %2;" : "=r"(r) : "f"(b), "f"(a));
    return r;
}
__device__ __forceinline__ void split2h(float f0, float f1, uint32_t& hi, uint32_t& lo) {
    __half a0 = __float2half_rn(f0), a1 = __float2half_rn(f1);
    hi = ((uint32_t)__half_as_ushort(a1) << 16) | __half_as_ushort(a0);
    lo = pack_f16x2(f0 - __half2float(a0), f1 - __half2float(a1));
}
__device__ __forceinline__ void ldmx4(uint32_t* r, uint32_t addr) {
    asm volatile("ldmatrix.sync.aligned.m8n8.x4.shared.b16 {%0,%1,%2,%3}, [%4];"
                 : "=r"(r[0]), "=r"(r[1]), "=r"(r[2]), "=r"(r[3]) : "r"(addr));
}
__device__ __forceinline__ void mma16816h(float* c, const uint32_t* a,
                                          const uint32_t* b) {
    asm volatile(
        "mma.sync.aligned.m16n8k16.row.col.f32.f16.f16.f32 "
        "{%0,%1,%2,%3}, {%4,%5,%6,%7}, {%8,%9}, {%0,%1,%2,%3};"
        : "+f"(c[0]), "+f"(c[1]), "+f"(c[2]), "+f"(c[3])
        : "r"(a[0]), "r"(a[1]), "r"(a[2]), "r"(a[3]), "r"(b[0]), "r"(b[1]));
}
__device__ __forceinline__ void cp16(uint32_t dst, const void* src) {
    asm volatile("cp.async.cg.shared.global [%0], [%1], 16;"
                 :: "r"(dst), "l"(src) : "memory");
}
__device__ __forceinline__ void cp_commit() {
    asm volatile("cp.async.commit_group;" ::: "memory");
}
__device__ __forceinline__ void cp_wait1() {
    asm volatile("cp.async.wait_group 1;" ::: "memory");
}
__device__ __forceinline__ void cp_wait0() {
    asm volatile("cp.async.wait_group 0;" ::: "memory");
}

// ---------------------------------------------------------------------------
// Kernel 0: convert x -> fp16 hi/lo; W -> W^T fp16 hi/lo.
// ---------------------------------------------------------------------------
__global__ void __launch_bounds__(256) pr_convert(
    const float* __restrict__ x,
    const float* __restrict__ Wq, const float* __restrict__ Wk,
    const float* __restrict__ Wv)
{
    const int bid = blockIdx.x, t = threadIdx.x;
    if (bid < 2048) {
        size_t e0 = ((size_t)bid * 256 + t) * 8;
        float4 f0 = *(const float4*)(x + e0);
        float4 f1 = *(const float4*)(x + e0 + 4);
        uint32_t h[4], l[4];
        split2h(f0.x, f0.y, h[0], l[0]);
        split2h(f0.z, f0.w, h[1], l[1]);
        split2h(f1.x, f1.y, h[2], l[2]);
        split2h(f1.z, f1.w, h[3], l[3]);
        *(uint4*)(g_xh + e0) = make_uint4(h[0], h[1], h[2], h[3]);
        *(uint4*)(g_xl + e0) = make_uint4(l[0], l[1], l[2], l[3]);
    } else {
        int idx = (bid - 2048) * 256 + t;
        int m   = idx >> 12;
        int rem = idx & 4095;
        int d   = rem >> 5;
        int k0  = (rem & 31) * 8;
        const float* W = (m == 0) ? Wq : ((m == 1) ? Wk : Wv);
        uint32_t h[4], l[4];
#pragma unroll
        for (int i = 0; i < 4; i++) {
            float a = W[(size_t)(k0 + 2 * i) * PR_D + d];
            float b = W[(size_t)(k0 + 2 * i + 1) * PR_D + d];
            split2h(a, b, h[i], l[i]);
        }
        size_t o = ((size_t)m * PR_D + d) * PR_INDIM + k0;
        *(uint4*)(g_WTh + o) = make_uint4(h[0], h[1], h[2], h[3]);
        *(uint4*)(g_WTl + o) = make_uint4(l[0], l[1], l[2], l[3]);
    }
}

// ---------------------------------------------------------------------------
// Kernel 1: HMMA projection, 3-pass split fp16 (unchanged).
// ---------------------------------------------------------------------------
#define XROW    528
#define SM_X    0
#define SM_WH   67584
#define SM_WL   135168
#define PROJ_SM 202752

__global__ void __launch_bounds__(256, 1) pr_proj_mma(
    const float* __restrict__ bq, const float* __restrict__ bk,
    const float* __restrict__ bv)
{
    extern __shared__ char sm[];
    const uint32_t sb = smem_u32(sm);

    const int t    = threadIdx.x;
    const int w    = t >> 5;
    const int lane = t & 31;
    const int qb   = blockIdx.x * 128;

    const uint32_t aoff = (uint32_t)(16 * w + (lane & 15)) * XROW
                        + (uint32_t)(lane >> 4) * 16;
    const uint32_t boff = (uint32_t)((lane & 7) + 8 * (lane >> 4)) * XROW
                        + (uint32_t)((lane >> 3) & 1) * 16;

#pragma unroll
    for (int i = 0; i < 16; i++) {
        int cid = t + i * 256;
        int r = cid >> 5, c = cid & 31;
        cp16(sb + SM_X + r * XROW + c * 16, g_xh + (size_t)(qb + r) * PR_INDIM + c * 8);
    }
    cp_commit();
    cp_wait0();
    __syncthreads();

    uint32_t xh[16][4];
#pragma unroll
    for (int kc = 0; kc < 16; kc++)
        ldmx4(xh[kc], sb + SM_X + aoff + kc * 32);
    __syncthreads();

#pragma unroll
    for (int i = 0; i < 16; i++) {
        int cid = t + i * 256;
        int r = cid >> 5, c = cid & 31;
        cp16(sb + SM_X + r * XROW + c * 16, g_xl + (size_t)(qb + r) * PR_INDIM + c * 8);
        cp16(sb + SM_WH + r * XROW + c * 16, g_WTh + (size_t)r * PR_INDIM + c * 8);
        cp16(sb + SM_WL + r * XROW + c * 16, g_WTl + (size_t)r * PR_INDIM + c * 8);
    }
    cp_commit();
    cp_wait0();
    __syncthreads();

    const float* bias[3] = {bq, bk, bv};
    const int r0 = qb + 16 * w + (lane >> 2);
    const int c0 = 2 * (lane & 3);

#pragma unroll 1
    for (int m = 0; m < 3; m++) {
        float acc[16][4];
#pragma unroll
        for (int nt = 0; nt < 16; nt++) {
            float b0 = bias[m][nt * 8 + c0];
            float b1 = bias[m][nt * 8 + c0 + 1];
            acc[nt][0] = b0; acc[nt][1] = b1;
            acc[nt][2] = b0; acc[nt][3] = b1;
        }

#pragma unroll
        for (int kc = 0; kc < 16; kc++) {
            uint32_t al[4];
            ldmx4(al, sb + SM_X + aoff + kc * 32);
#pragma unroll
            for (int h = 0; h < 2; h++) {
                uint32_t Bh[4][4], Bl[4][4];
#pragma unroll
                for (int j = 0; j < 4; j++) {
                    uint32_t ro = (uint32_t)(h * 64 + j * 16) * XROW + kc * 32;
                    ldmx4(Bh[j], sb + SM_WH + boff + ro);
                    ldmx4(Bl[j], sb + SM_WL + boff + ro);
                }
#pragma unroll
                for (int j = 0; j < 4; j++) {
                    mma16816h(acc[h * 8 + 2 * j],     xh[kc], &Bh[j][0]);
                    mma16816h(acc[h * 8 + 2 * j + 1], xh[kc], &Bh[j][2]);
                }
#pragma unroll
                for (int j = 0; j < 4; j++) {
                    mma16816h(acc[h * 8 + 2 * j],     al, &Bh[j][0]);
                    mma16816h(acc[h * 8 + 2 * j + 1], al, &Bh[j][2]);
                }
#pragma unroll
                for (int j = 0; j < 4; j++) {
                    mma16816h(acc[h * 8 + 2 * j],     xh[kc], &Bl[j][0]);
                    mma16816h(acc[h * 8 + 2 * j + 1], xh[kc], &Bl[j][2]);
                }
            }
        }

        if (m < 2) {
            __half* D = (m == 0) ? g_Qh : g_Kh;
#pragma unroll
            for (int nt = 0; nt < 16; nt++) {
                int col = nt * 8 + c0;
                *(uint32_t*)(D + (size_t)r0 * PR_D + col)
                    = pack_f16x2(acc[nt][0], acc[nt][1]);
                *(uint32_t*)(D + (size_t)(r0 + 8) * PR_D + col)
                    = pack_f16x2(acc[nt][2], acc[nt][3]);
            }
        } else {
            __syncthreads();
            const int rl = 16 * w + (lane >> 2);
#pragma unroll
            for (int nt = 0; nt < 16; nt++) {
                int col = nt * 8 + c0;
                *(uint32_t*)(sm + rl * 272 + col * 2)
                    = pack_f16x2(acc[nt][0], acc[nt][1]);
                *(uint32_t*)(sm + (rl + 8) * 272 + col * 2)
                    = pack_f16x2(acc[nt][2], acc[nt][3]);
            }
            __syncthreads();
            const int d  = t >> 1;
            const int hf = t & 1;
            uint32_t u[32];
#pragma unroll
            for (int j = 0; j < 32; j++) {
                uint32_t a = *(const uint16_t*)(sm + (hf * 64 + 2 * j) * 272 + d * 2);
                uint32_t b = *(const uint16_t*)(sm + (hf * 64 + 2 * j + 1) * 272 + d * 2);
                u[j] = (b << 16) | a;
            }
            uint4* dst = (uint4*)(g_VTh + (size_t)d * PR_N + qb + hf * 64);
#pragma unroll
            for (int q = 0; q < 8; q++)
                dst[q] = make_uint4(u[4 * q], u[4 * q + 1], u[4 * q + 2], u[4 * q + 3]);
        }

        if (m < 2) {
            __syncthreads();
#pragma unroll
            for (int i = 0; i < 16; i++) {
                int cid = t + i * 256;
                int r = cid >> 5, c = cid & 31;
                size_t o = (size_t)(m + 1) * PR_D * PR_INDIM + (size_t)r * PR_INDIM + c * 8;
                cp16(sb + SM_WH + r * XROW + c * 16, g_WTh + o);
                cp16(sb + SM_WL + r * XROW + c * 16, g_WTl + o);
            }
            cp_commit();
            cp_wait0();
            __syncthreads();
        }
    }
}

// ---------------------------------------------------------------------------
// Kernel 2: HMMA flash attention, split-K x16, 32 q-rows per warp.
// CTA = 256 thr (8 warps), 256 q-rows.  grid = 1024 (64 qt x 16 ks).
// Q in smem (re-read per kc); warp w owns rows [32w, 32w+32) (2 m-tiles).
// 3 smem stages, one barrier per subtile.
// ---------------------------------------------------------------------------
#define ATH    256
#define KROW   272
#define VROW   144
#define OFF_K  0
#define OFF_V  17408
#define ST_BYTES 35840
#define SM_Q     0                      // 256 rows x 272 B = 69632
#define SM_ST    69632
#define SM_BYTES (SM_ST + 3 * ST_BYTES) // 177152

__device__ __forceinline__ void load_stage(uint32_t dst, int kb)
{
    const int t = threadIdx.x;
#pragma unroll
    for (int i = 0; i < 4; i++) {
        int cid = t + i * ATH;               // 1024: 64 rows x 16 chunks
        int r = cid >> 4, c = cid & 15;
        cp16(dst + OFF_K + r * KROW + c * 16, g_Kh + (size_t)(kb + r) * PR_D + c * 8);
    }
#pragma unroll
    for (int i = 0; i < 4; i++) {
        int cid = t + i * ATH;               // 1024: 128 d x 8 chunks
        int r = cid >> 3, c = cid & 7;
        cp16(dst + OFF_V + r * VROW + c * 16, g_VTh + (size_t)r * PR_N + kb + c * 8);
    }
}

__global__ void __launch_bounds__(ATH, 1) pr_attn_mma()
{
    extern __shared__ char sm[];
    const uint32_t sb = smem_u32(sm);

    const int t     = threadIdx.x;
    const int w     = t >> 5;
    const int lane  = t & 31;
    const int qb    = (blockIdx.x >> 4) * 256;
    const int ks    = blockIdx.x & 15;
    const int kbase = ks * KEYS_PER;

    // Q A-fragment smem offsets for the warp's two m-tiles
    const uint32_t aQ0 = sb + SM_Q + (uint32_t)(32 * w + (lane & 15)) * KROW
                       + (uint32_t)(lane >> 4) * 16;
    const uint32_t aQ1 = aQ0 + 16 * KROW;
    const uint32_t bRow = (uint32_t)((lane & 7) + 8 * (lane >> 4));
    const uint32_t bCol = (uint32_t)((lane >> 3) & 1);
    const uint32_t bKoff = bRow * KROW + bCol * 16;
    const uint32_t bVoff = bRow * VROW + bCol * 16;

    // ---- stage Q (256 rows, resident all loop) ----
#pragma unroll
    for (int i = 0; i < 16; i++) {
        int cid = t + i * ATH;               // 4096: 256 rows x 16 chunks
        int r = cid >> 4, c = cid & 15;
        cp16(sb + SM_Q + r * KROW + c * 16, g_Qh + (size_t)(qb + r) * PR_D + c * 8);
    }
    cp_commit();

    float o[2][16][4];
#pragma unroll
    for (int mi = 0; mi < 2; mi++)
#pragma unroll
        for (int i = 0; i < 16; i++)
#pragma unroll
            for (int j = 0; j < 4; j++) o[mi][i][j] = 0.0f;
    float lsum[2][2] = {{0.0f, 0.0f}, {0.0f, 0.0f}};
    float M[2][2]    = {{-1e30f, -1e30f}, {-1e30f, -1e30f}};

    // prologue: tiles 0,1 (Q group ahead of them; wait1 in loop covers all)
    load_stage(sb + SM_ST + 0 * ST_BYTES, kbase);
    cp_commit();
    load_stage(sb + SM_ST + 1 * ST_BYTES, kbase + 64);
    cp_commit();

    int st_cur = 0, st_pre = 2;
#pragma unroll 1
    for (int tt = 0; tt < NTS; tt++) {
        cp_wait1();                  // Q + tiles through tt landed (tt+1 in flight)
        __syncthreads();
        if (tt + 2 < NTS) load_stage(sb + SM_ST + st_pre * ST_BYTES, kbase + (tt + 2) * 64);
        cp_commit();                 // commit every iter: group FIFO stays aligned

        const uint32_t p   = sb + SM_ST + st_cur * ST_BYTES;
        const uint32_t bKh = p + OFF_K + bKoff;
        const uint32_t bVh = p + OFF_V + bVoff;

        // ---- S = Q K^T, 32 rows x 64 keys per warp ----
        float s[2][8][4];
#pragma unroll
        for (int mi = 0; mi < 2; mi++)
#pragma unroll
            for (int i = 0; i < 8; i++)
#pragma unroll
                for (int j = 0; j < 4; j++) s[mi][i][j] = 0.0f;

#pragma unroll
        for (int kc = 0; kc < 8; kc++) {
            uint32_t qa0[4], qa1[4];
            ldmx4(qa0, aQ0 + kc * 32);
            ldmx4(qa1, aQ1 + kc * 32);
            uint32_t bh[4][4];
#pragma unroll
            for (int jn = 0; jn < 4; jn++)
                ldmx4(bh[jn], bKh + jn * (16 * KROW) + kc * 32);
#pragma unroll
            for (int jn = 0; jn < 4; jn++) {
                mma16816h(s[0][2 * jn],     qa0, &bh[jn][0]);
                mma16816h(s[0][2 * jn + 1], qa0, &bh[jn][2]);
            }
#pragma unroll
            for (int jn = 0; jn < 4; jn++) {
                mma16816h(s[1][2 * jn],     qa1, &bh[jn][0]);
                mma16816h(s[1][2 * jn + 1], qa1, &bh[jn][2]);
            }
        }

        // ---- flash softmax per m-tile ----
        uint32_t pp[2][16];
#pragma unroll
        for (int mi = 0; mi < 2; mi++) {
            float m0 = s[mi][0][0], m1 = s[mi][0][2];
#pragma unroll
            for (int jt = 0; jt < 8; jt++) {
                m0 = fmaxf(m0, fmaxf(s[mi][jt][0], s[mi][jt][1]));
                m1 = fmaxf(m1, fmaxf(s[mi][jt][2], s[mi][jt][3]));
            }
            m0 = fmaxf(m0, __shfl_xor_sync(0xffffffffu, m0, 1));
            m0 = fmaxf(m0, __shfl_xor_sync(0xffffffffu, m0, 2));
            m1 = fmaxf(m1, __shfl_xor_sync(0xffffffffu, m1, 1));
            m1 = fmaxf(m1, __shfl_xor_sync(0xffffffffu, m1, 2));

            if (m0 > M[mi][0] || m1 > M[mi][1]) {
                const float M0n = fmaxf(M[mi][0], m0), M1n = fmaxf(M[mi][1], m1);
                const float sc0 = ex2f((M[mi][0] - M0n) * LOG2E);
                const float sc1 = ex2f((M[mi][1] - M1n) * LOG2E);
                M[mi][0] = M0n; M[mi][1] = M1n;
                lsum[mi][0] *= sc0;
                lsum[mi][1] *= sc1;
#pragma unroll
                for (int dt = 0; dt < 16; dt++) {
                    o[mi][dt][0] *= sc0; o[mi][dt][1] *= sc0;
                    o[mi][dt][2] *= sc1; o[mi][dt][3] *= sc1;
                }
            }
            const float b0 = M[mi][0] * LOG2E, b1 = M[mi][1] * LOG2E;
            float ts0 = 0.0f, ts1 = 0.0f;
#pragma unroll
            for (int jt = 0; jt < 8; jt++) {
                float e0 = ex2f(fmaf(s[mi][jt][0], LOG2E, -b0));
                float e1 = ex2f(fmaf(s[mi][jt][1], LOG2E, -b0));
                float e2 = ex2f(fmaf(s[mi][jt][2], LOG2E, -b1));
                float e3 = ex2f(fmaf(s[mi][jt][3], LOG2E, -b1));
                ts0 += e0 + e1;
                ts1 += e2 + e3;
                pp[mi][2 * jt]     = pack_f16x2(e0, e1);
                pp[mi][2 * jt + 1] = pack_f16x2(e2, e3);
            }
            lsum[mi][0] += ts0;
            lsum[mi][1] += ts1;
        }

        // ---- O += P V, both m-tiles share each V fragment ----
        uint32_t v[2][4];
        ldmx4(v[0], bVh);
#pragma unroll
        for (int idx = 0; idx < 32; idx++) {
            const int cur = idx & 1, nxt = cur ^ 1;
            if (idx < 31) {
                const int kc2 = (idx + 1) >> 3, dn2 = (idx + 1) & 7;
                ldmx4(v[nxt], bVh + dn2 * (16 * VROW) + kc2 * 32);
            }
            const int kc = idx >> 3, dn = idx & 7;
            mma16816h(o[0][2 * dn],     &pp[0][4 * kc], &v[cur][0]);
            mma16816h(o[0][2 * dn + 1], &pp[0][4 * kc], &v[cur][2]);
            mma16816h(o[1][2 * dn],     &pp[1][4 * kc], &v[cur][0]);
            mma16816h(o[1][2 * dn + 1], &pp[1][4 * kc], &v[cur][2]);
        }

        st_cur = (st_cur == 2) ? 0 : st_cur + 1;
        st_pre = (st_pre == 2) ? 0 : st_pre + 1;
    }

    // ---- epilogue: normalize, write fp16 partials + (M, lsum) ----
    __half* pO = g_pO + ((size_t)ks * PR_N) * PR_D;
    const int cb = 2 * (lane & 3);
#pragma unroll
    for (int mi = 0; mi < 2; mi++) {
        float l0 = lsum[mi][0], l1 = lsum[mi][1];
        l0 += __shfl_xor_sync(0xffffffffu, l0, 1);
        l0 += __shfl_xor_sync(0xffffffffu, l0, 2);
        l1 += __shfl_xor_sync(0xffffffffu, l1, 1);
        l1 += __shfl_xor_sync(0xffffffffu, l1, 2);
        const float inv0 = 1.0f / l0;
        const float inv1 = 1.0f / l1;
        const int r0 = qb + 32 * w + 16 * mi + (lane >> 2);
#pragma unroll
        for (int dt = 0; dt < 16; dt++) {
            *(uint32_t*)(pO + (size_t)r0 * PR_D + 8 * dt + cb)
                = pack_f16x2(o[mi][dt][0] * inv0, o[mi][dt][1] * inv0);
            *(uint32_t*)(pO + (size_t)(r0 + 8) * PR_D + 8 * dt + cb)
                = pack_f16x2(o[mi][dt][2] * inv1, o[mi][dt][3] * inv1);
        }
        if ((lane & 3) == 0) {
            g_pM[ks * PR_N + r0]     = M[mi][0];
            g_pL[ks * PR_N + r0]     = l0;
            g_pM[ks * PR_N + r0 + 8] = M[mi][1];
            g_pL[ks * PR_N + r0 + 8] = l1;
        }
    }
}

// ---------------------------------------------------------------------------
// Kernel 3: merge 16 normalized fp16 partials.  grid=1024 x 256.
// ---------------------------------------------------------------------------
__global__ void __launch_bounds__(256) pr_merge(float* __restrict__ out)
{
    const int g   = blockIdx.x * 256 + threadIdx.x;   // 262144
    const int row = g >> 4;
    const int c8  = (g & 15) * 8;

    float M = -1e30f;
#pragma unroll
    for (int i = 0; i < KSPLIT; i++)
        M = fmaxf(M, g_pM[i * PR_N + row]);

    float wsum = 0.0f;
    float acc[8];
#pragma unroll
    for (int j = 0; j < 8; j++) acc[j] = 0.0f;

#pragma unroll
    for (int i = 0; i < KSPLIT; i++) {
        float wgt = g_pL[i * PR_N + row] * ex2f((g_pM[i * PR_N + row] - M) * LOG2E);
        wsum += wgt;
        uint4 raw = *(const uint4*)(g_pO + ((size_t)i * PR_N + row) * PR_D + c8);
        const uint32_t* rw = &raw.x;
#pragma unroll
        for (int j = 0; j < 4; j++) {
            float2 v = __half22float2(*(const __half2*)&rw[j]);
            acc[2 * j]     = fmaf(v.x, wgt, acc[2 * j]);
            acc[2 * j + 1] = fmaf(v.y, wgt, acc[2 * j + 1]);
        }
    }
    const float inv = 1.0f / wsum;
    float4 o0, o1;
    o0.x = acc[0] * inv; o0.y = acc[1] * inv;
    o0.z = acc[2] * inv; o0.w = acc[3] * inv;
    o1.x = acc[4] * inv; o1.y = acc[5] * inv;
    o1.z = acc[6] * inv; o1.w = acc[7] * inv;
    float4* dst = (float4*)(out + (size_t)row * PR_D + c8);
    dst[0] = o0;
    dst[1] = o1;
}

// ---------------------------------------------------------------------------
extern "C" void kernel_launch(void* const* d_in, const int* in_sizes, int n_in,
                              void* d_out, int out_size)
{
    const float* x  = (const float*)d_in[0];
    const float* Wq = (const float*)d_in[1];
    const float* bq = (const float*)d_in[2];
    const float* Wk = (const float*)d_in[3];
    const float* bk = (const float*)d_in[4];
    const float* Wv = (const float*)d_in[5];
    const float* bv = (const float*)d_in[6];
    float* out = (float*)d_out;

    pr_convert<<<2096, 256>>>(x, Wq, Wk, Wv);

    cudaFuncSetAttribute(pr_proj_mma,
                         cudaFuncAttributeMaxDynamicSharedMemorySize, PROJ_SM);
    pr_proj_mma<<<PR_N / 128, 256, PROJ_SM>>>(bq, bk, bv);

    cudaFuncSetAttribute(pr_attn_mma,
                         cudaFuncAttributeMaxDynamicSharedMemorySize, SM_BYTES);
    pr_attn_mma<<<(PR_N / 256) * KSPLIT, ATH, SM_BYTES>>>();

    pr_merge<<<1024, 256>>>(out);
}